// round 9
// baseline (speedup 1.0000x reference)
#include <cuda_runtime.h>
#include <cuda_bf16.h>
#include <cstdint>
#include <math.h>

#define NNODES 4096
#define NW 128
#define NHEADS 4

typedef unsigned long long ull;

// ---------------- scratch ----------------
__device__ unsigned g_adjbits[NNODES * NW];
__device__ float g_hf[NHEADS * NNODES * 128];
__device__ float g_f1[NHEADS * NNODES];
__device__ float g_f2[NHEADS * NNODES];
__device__ float g_E1[NHEADS * NNODES];
__device__ float g_E1s[NHEADS * NNODES];
__device__ float g_E2[NHEADS * NNODES];
__device__ float g_E2s[NHEADS * NNODES];
__device__ float g_cat1[NNODES * 512];
__device__ float g_cat2[NNODES * 256];
__device__ float g_h3[NNODES * 16];
__device__ float g_hT[NHEADS * 128 * NNODES];    // [h][d][m], tf32-rounded fp32

__device__ __forceinline__ float eluf(float v) { return v > 0.f ? v : expm1f(v); }

__device__ __forceinline__ uint32_t smem_u32(const void* p) {
    uint32_t a;
    asm("{ .reg .u64 t; cvta.to.shared.u64 t, %1; cvt.u32.u64 %0, t; }" : "=r"(a) : "l"(p));
    return a;
}
__device__ __forceinline__ uint32_t tf32u(float v) {
    uint32_t r;
    asm("cvt.rna.tf32.f32 %0, %1;" : "=r"(r) : "f"(v));
    return r;
}

#define CP16(dst, src) \
    asm volatile("cp.async.cg.shared.global [%0], [%1], 16;" :: "r"(dst), "l"(src))
#define CP_COMMIT() asm volatile("cp.async.commit_group;" ::: "memory")
#define CP_WAIT(n)  asm volatile("cp.async.wait_group %0;" :: "n"(n) : "memory")

__device__ __forceinline__ void mma_tf32(float* c, uint32_t a0, uint32_t a1,
                                         uint32_t a2, uint32_t a3,
                                         uint32_t b0, uint32_t b1) {
    asm volatile(
        "mma.sync.aligned.m16n8k8.row.col.f32.tf32.tf32.f32 "
        "{%0,%1,%2,%3}, {%4,%5,%6,%7}, {%8,%9}, {%0,%1,%2,%3};"
        : "+f"(c[0]), "+f"(c[1]), "+f"(c[2]), "+f"(c[3])
        : "r"(a0), "r"(a1), "r"(a2), "r"(a3), "r"(b0), "r"(b1));
}

// ---------------- feature GEMM ----------------
template<int TN, int TD, int MR, int NC, int SRC>
__global__ __launch_bounds__(256) void gemm_k(const float* __restrict__ Aext,
                                              const float* __restrict__ W,
                                              int K, int Dtot) {
    const int TK = 16;
    __shared__ float As[TK][TN];
    __shared__ float Bs[TK][TD];
    const float* A = (SRC == 0) ? Aext : (SRC == 1 ? g_cat1 : g_cat2);

    int t = threadIdx.x;
    int n0 = blockIdx.x * TN;
    int d0 = blockIdx.y * TD;
    int h  = blockIdx.z;
    const float* Wh = W + (size_t)h * K * Dtot;
    const int rg = t / (TD / NC);
    const int cg = t % (TD / NC);

    float acc[MR][NC];
#pragma unroll
    for (int i = 0; i < MR; i++)
#pragma unroll
        for (int j = 0; j < NC; j++) acc[i][j] = 0.f;

    for (int k0 = 0; k0 < K; k0 += TK) {
        for (int idx = t; idx < TN * (TK / 4); idx += 256) {
            int i_n = idx / (TK / 4);
            int k4  = idx % (TK / 4);
            float4 v = *(const float4*)&A[(size_t)(n0 + i_n) * K + k0 + 4 * k4];
            As[4 * k4 + 0][i_n] = v.x;
            As[4 * k4 + 1][i_n] = v.y;
            As[4 * k4 + 2][i_n] = v.z;
            As[4 * k4 + 3][i_n] = v.w;
        }
        for (int idx = t; idx < TK * (TD / 4); idx += 256) {
            int kk = idx / (TD / 4);
            int j4 = idx % (TD / 4);
            *(float4*)&Bs[kk][4 * j4] =
                *(const float4*)&Wh[(size_t)(k0 + kk) * Dtot + d0 + 4 * j4];
        }
        __syncthreads();
#pragma unroll
        for (int k = 0; k < TK; k++) {
            float a_[MR], b_[NC];
#pragma unroll
            for (int i = 0; i < MR; i++) a_[i] = As[k][rg * MR + i];
#pragma unroll
            for (int j = 0; j < NC; j++) b_[j] = Bs[k][cg * NC + j];
#pragma unroll
            for (int i = 0; i < MR; i++)
#pragma unroll
                for (int j = 0; j < NC; j++)
                    acc[i][j] = fmaf(a_[i], b_[j], acc[i][j]);
        }
        __syncthreads();
    }
    float* Ch = g_hf + (size_t)h * NNODES * Dtot;
#pragma unroll
    for (int i = 0; i < MR; i++)
#pragma unroll
        for (int j = 0; j < NC; j++)
            Ch[(size_t)(n0 + rg * MR + i) * Dtot + d0 + cg * NC + j] = acc[i][j];
}

// ---------------- scores (optionally fused with adjacency bit-pack) ----------------
__device__ __forceinline__ void scores_body(const float* a, int D, int total,
                                            int blk, int t) {
    int gid  = blk * 8 + (t >> 5);
    int lane = t & 31;
    if (gid >= total) return;
    int h = gid / NNODES, n = gid % NNODES;
    const float* hr = g_hf + ((size_t)h * NNODES + n) * D;
    const float* a1 = a + (size_t)h * 2 * D;
    const float* a2 = a1 + D;
    float s1 = 0.f, s2 = 0.f;
    for (int d = lane; d < D; d += 32) {
        float v = hr[d];
        s1 += v * a1[d];
        s2 += v * a2[d];
    }
#pragma unroll
    for (int o = 16; o; o >>= 1) {
        s1 += __shfl_xor_sync(~0u, s1, o);
        s2 += __shfl_xor_sync(~0u, s2, o);
    }
    if (!lane) {
        int idx = h * NNODES + n;
        g_f1[idx]  = s1;
        g_f2[idx]  = s2;
        g_E1[idx]  = expf(s1);
        g_E1s[idx] = expf(0.2f * s1);
        g_E2[idx]  = expf(s2);
        g_E2s[idx] = expf(0.2f * s2);
    }
}

__global__ __launch_bounds__(256) void scores_k(const float* __restrict__ a, int D, int total) {
    scores_body(a, D, total, blockIdx.x, threadIdx.x);
}

// blocks [0, scoreBlocks) do scores; blocks beyond do adjacency packing
__global__ __launch_bounds__(256) void scores_pack_k(const float* __restrict__ a, int D,
                                                     int total, const int* __restrict__ adj,
                                                     int scoreBlocks) {
    if ((int)blockIdx.x < scoreBlocks) {
        scores_body(a, D, total, blockIdx.x, threadIdx.x);
        return;
    }
    int wi = (blockIdx.x - scoreBlocks) * 256 + threadIdx.x;
    if (wi >= NNODES * NW) return;
    const int4* p = (const int4*)adj + (size_t)wi * 8;
    unsigned w = 0;
#pragma unroll
    for (int q = 0; q < 8; q++) {
        int4 v = p[q];
        if (v.x > 0) w |= 1u << (q * 4 + 0);
        if (v.y > 0) w |= 1u << (q * 4 + 1);
        if (v.z > 0) w |= 1u << (q * 4 + 2);
        if (v.w > 0) w |= 1u << (q * 4 + 3);
    }
    g_adjbits[wi] = w;
}

// ---------------- transpose + tf32 round: g_hf[h][n][d] -> g_hT[h][d][m] ----------------
template<int D>
__global__ __launch_bounds__(256) void transpose_tf32_k() {
    __shared__ float ts[32][33];
    int t  = threadIdx.x;
    int nt = blockIdx.x, dt = blockIdx.y, h = blockIdx.z;
    int r0 = t / 32, c = t % 32;
#pragma unroll
    for (int p = 0; p < 4; p++) {
        int r = p * 8 + r0;
        ts[r][c] = g_hf[((size_t)h * NNODES + nt * 32 + r) * D + dt * 32 + c];
    }
    __syncthreads();
#pragma unroll
    for (int p = 0; p < 4; p++) {
        int dr = p * 8 + r0;
        uint32_t v = tf32u(ts[c][dr]);
        size_t addr = ((size_t)h * D + dt * 32 + dr) * NNODES + nt * 32 + c;
        g_hT[addr] = __uint_as_float(v);
    }
}

// ---------------- tf32 mma aggregation, shared-weight version ----------------
// CTA: 32 n-rows x D d-cols. Warps = 2 Mg x (D/32) Ng. Threads = 64*D/32.
// Weights for each 64-m chunk computed ONCE into smem (tf32), consumed as
// A-fragments by all warps. B/E double-buffered cp.async. 2 barriers/chunk.
template<int D>
__global__ __launch_bounds__(64 * (D / 32)) void aggW_k(const float* __restrict__ resid) {
    constexpr int NGW = D / 32;
    constexpr int TB  = 64 * NGW;
    constexpr int NCH = NNODES / 64;
    constexpr int WPT = 2048 / TB;          // weights per thread per chunk
    constexpr int TPR = TB / 32;            // threads per n-row
    constexpr int BST = 68;                 // B row stride (floats)
    constexpr int BBUF = D * BST * 4;       // bytes per B buffer
    constexpr int O_E  = 2 * BBUF;
    constexpr int O_W  = O_E + 2 * 768;
    constexpr int O_ZS = O_W + 32 * 68 * 4;

    extern __shared__ __align__(16) char sm[];
    const uint32_t sb = smem_u32(sm);
    float* Wsm = (float*)(sm + O_W);
    float* Zs  = (float*)(sm + O_ZS);

    const int t = threadIdx.x, lane = t & 31, wid = t >> 5;
    const int Mg = wid & 1, Ng = wid >> 1;
    const int n0 = blockIdx.x * 32;
    const int head = blockIdx.y;
    const int headN = head * NNODES;
    const int rq  = lane >> 2;
    const int k0b = lane & 3;

    // weight-compute assignment (fixed row per thread)
    const int wr   = t / TPR;               // n-row 0..31
    const int mseg = (t % TPR) * WPT;       // m offset within chunk
    const int msh  = mseg & 31;
    const float f1r  = g_f1[headN + n0 + wr];
    const float E1r  = g_E1[headN + n0 + wr];
    const float E1sr = g_E1s[headN + n0 + wr];
    const unsigned* adjp = g_adjbits + (size_t)(n0 + wr) * NW + (mseg >> 5);
    float zacc = 0.f;

    float acc[4][4];
#pragma unroll
    for (int a = 0; a < 4; a++)
#pragma unroll
        for (int q = 0; q < 4; q++) acc[a][q] = 0.f;

    auto fill = [&](int chunk, int buf) {
        for (int idx = t; idx < D * 16; idx += TB) {
            int row = idx >> 4, c16 = idx & 15;
            uint32_t dst = sb + (uint32_t)(buf * BBUF + row * (BST * 4) + c16 * 16);
            size_t s = ((size_t)(head * D + row)) * NNODES + chunk * 64 + c16 * 4;
            CP16(dst, (const void*)(g_hT + s));
        }
        if (t < 48) {
            int a = t >> 4, q = t & 15;
            const float* s = (a == 0 ? g_f2 : a == 1 ? g_E2 : g_E2s) +
                             headN + chunk * 64 + q * 4;
            uint32_t dst = sb + (uint32_t)(O_E + buf * 768 + a * 256 + q * 16);
            CP16(dst, (const void*)s);
        }
    };

    unsigned mcur = adjp[0];

    fill(0, 0); CP_COMMIT();

    for (int c = 0; c < NCH; c++) {
        const int buf = c & 1;
        CP_WAIT(0);                 // fill(c) data resident
        __syncthreads();            // visible to all; prev chunk's reads done
        if (c + 1 < NCH) { fill(c + 1, buf ^ 1); CP_COMMIT(); }
        unsigned mnext = (c + 1 < NCH) ? adjp[2 * (c + 1)] : 0u;

        // ---- weight tile: WPT weights in row wr, m in [mseg, mseg+WPT) ----
        {
            const float* f2c  = (const float*)(sm + O_E + buf * 768);
            const float* E2c  = f2c + 64;
            const float* E2sc = f2c + 128;
            unsigned mb = mcur >> msh;
            float* wrow = Wsm + wr * 68;
#pragma unroll
            for (int j = 0; j < WPT; j++) {
                int m = mseg + j;
                float s  = f1r + f2c[m];
                bool  pos = (s >= 0.f);
                float w = (pos ? E1r : E1sr) * (pos ? E2c[m] : E2sc[m]);
                w = ((mb >> j) & 1u) ? w : 0.f;
                zacc += w;
                wrow[m] = __uint_as_float(tf32u(w));
            }
        }
        __syncthreads();            // W visible

        // ---- mma over chunk: 8 k-steps of 8 ----
        const float* Bs = (const float*)(sm + buf * BBUF);
#pragma unroll
        for (int ks = 0; ks < 8; ks++) {
            const int mb = ks * 8 + k0b;
            const float* ar0 = Wsm + (Mg * 16 + rq) * 68 + mb;
            const float* ar1 = ar0 + 8 * 68;
            uint32_t a0 = __float_as_uint(ar0[0]);
            uint32_t a1 = __float_as_uint(ar1[0]);
            uint32_t a2 = __float_as_uint(ar0[4]);
            uint32_t a3 = __float_as_uint(ar1[4]);
#pragma unroll
            for (int ng = 0; ng < 4; ng++) {
                const int drow = Ng * 32 + ng * 8 + rq;
                float b0 = Bs[drow * BST + mb];
                float b1 = Bs[drow * BST + mb + 4];
                mma_tf32(acc[ng], a0, a1, a2, a3,
                         __float_as_uint(b0), __float_as_uint(b1));
            }
        }
        mcur = mnext;
    }

    // ---- Z: reduce across TPR threads sharing a row ----
    {
        float z = zacc;
#pragma unroll
        for (int o = TPR / 2; o; o >>= 1) z += __shfl_xor_sync(~0u, z, o);
        if ((t % TPR) == 0) Zs[wr] = 1.f / z;
    }
    __syncthreads();

    float* out = (D == 128) ? g_cat1 : g_cat2;
    const int ostr = (D == 128) ? 512 : 256;
#pragma unroll
    for (int i = 0; i < 2; i++) {
        int lr = Mg * 16 + rq + i * 8;
        int n  = n0 + lr;
        float zi = Zs[lr];
#pragma unroll
        for (int nt = 0; nt < 4; nt++) {
            int col = Ng * 32 + nt * 8 + (lane & 3) * 2;
            float v0 = acc[nt][2 * i]     * zi;
            float v1 = acc[nt][2 * i + 1] * zi;
            if (D == 128) {
                float2 rx = *(const float2*)&resid[(size_t)n * 128 + col];
                v0 += rx.x; v1 += rx.y;
            }
            float2 o = {eluf(v0), eluf(v1)};
            *(float2*)&out[(size_t)n * ostr + head * D + col] = o;
        }
    }
}

// ---------------- SIMT agg for layer 3 (D=16) ----------------
__device__ __forceinline__ ull dupf(float v) {
    ull r; asm("mov.b64 %0, {%1, %1};" : "=l"(r) : "f"(v)); return r;
}
__device__ __forceinline__ void ffma2(ull& acc, ull a, ull b) {
    asm("fma.rn.f32x2 %0, %1, %2, %0;" : "+l"(acc) : "l"(a), "l"(b));
}
__device__ __forceinline__ float2 unpack2(ull v) {
    float2 r; asm("mov.b64 {%0, %1}, %2;" : "=f"(r.x), "=f"(r.y) : "l"(v)); return r;
}

__global__ __launch_bounds__(128) void agg3_k() {
    const int D = 16, TN = 32, TM = 32, MR = 2, NC = 2;
    __shared__ __align__(16) float hs[2][TM][D];
    __shared__ __align__(16) float ws[2][TM][TN + 2];
    __shared__ float Zred[128];
    __shared__ float Zs[TN];

    const int t  = threadIdx.x;
    const int n0 = blockIdx.x * TN;
    const float* hfh = g_hf;

    const int rA = t % TN;
    const int G  = 128 / TN;
    const int g  = t / TN;
    const int MMPT = TM / G;

    const float rf1  = g_f1[n0 + rA];
    const float rE1  = g_E1[n0 + rA];
    const float rE1s = g_E1s[n0 + rA];
    float zacc = 0.f;

    const int rg = t / (D / NC);
    const int cg = t % (D / NC);

    ull acc[NC];
#pragma unroll
    for (int j = 0; j < NC; j++) acc[j] = 0ull;

    auto fill = [&](int wti, int buf) {
        int m0 = wti * TM;
        for (int idx = t; idx < TM * (D / 4); idx += 128) {
            int m  = idx / (D / 4);
            int dd = idx % (D / 4);
            *(float4*)&hs[buf][m][4 * dd] = *(const float4*)&hfh[(size_t)(m0 + m) * D + 4 * dd];
        }
        unsigned aw = g_adjbits[(size_t)(n0 + rA) * NW + wti];
#pragma unroll
        for (int j = 0; j < MMPT; j++) {
            int mm = g + G * j;
            float w = 0.f;
            if ((aw >> mm) & 1u) {
                float s = rf1 + g_f2[m0 + mm];
                w = (s >= 0.f) ? rE1 * g_E2[m0 + mm] : rE1s * g_E2s[m0 + mm];
            }
            ws[buf][mm][rA] = w;
            zacc += w;
        }
    };

    fill(0, 0);
    __syncthreads();
    const int NT = NNODES / TM;
    for (int mt = 0; mt < NT; mt++) {
        int cur = mt & 1;
        if (mt + 1 < NT) fill(mt + 1, cur ^ 1);
#pragma unroll
        for (int k = 0; k < TM; k++) {
            ull a2 = *(const ull*)&ws[cur][k][rg * MR];
#pragma unroll
            for (int j = 0; j < NC; j++) {
                ull bb = dupf(hs[cur][k][cg * NC + j]);
                ffma2(acc[j], a2, bb);
            }
        }
        __syncthreads();
    }
    Zred[t] = zacc;
    __syncthreads();
    if (t < TN) {
        float z = 0.f;
#pragma unroll
        for (int q = 0; q < G; q++) z += Zred[t + q * TN];
        Zs[t] = 1.f / z;
    }
    __syncthreads();
    {
        int lr0 = rg * MR;
        float zi0 = Zs[lr0], zi1 = Zs[lr0 + 1];
#pragma unroll
        for (int j = 0; j < NC; j++) {
            float2 v = unpack2(acc[j]);
            int d = cg * NC + j;
            g_h3[(size_t)(n0 + lr0) * 16 + d]     = eluf(v.x * zi0);
            g_h3[(size_t)(n0 + lr0 + 1) * 16 + d] = eluf(v.y * zi1);
        }
    }
}

// ---------------- final log-softmax ----------------
__global__ __launch_bounds__(256) void logsoftmax_k(float* __restrict__ out) {
    int n    = blockIdx.x * 8 + (threadIdx.x >> 5);
    int lane = threadIdx.x & 31;
    if (n >= NNODES) return;
    float v = (lane < 16) ? g_h3[n * 16 + lane] : -INFINITY;
    float m = v;
#pragma unroll
    for (int o = 16; o; o >>= 1) m = fmaxf(m, __shfl_xor_sync(~0u, m, o));
    float e = (lane < 16) ? expf(v - m) : 0.f;
    float s = e;
#pragma unroll
    for (int o = 16; o; o >>= 1) s += __shfl_xor_sync(~0u, s, o);
    if (lane < 16) out[n * 16 + lane] = v - m - logf(s);
}

// ---------------- launch ----------------
extern "C" void kernel_launch(void* const* d_in, const int* in_sizes, int n_in,
                              void* d_out, int out_size) {
    const float* x     = (const float*)d_in[0];
    const int*   adj   = (const int*)d_in[1];
    const float* W_in  = (const float*)d_in[2];
    const float* a_in  = (const float*)d_in[3];
    const float* W_hid = (const float*)d_in[4];
    const float* a_hid = (const float*)d_in[5];
    const float* W_out = (const float*)d_in[6];
    const float* a_out = (const float*)d_in[7];
    float* out = (float*)d_out;

    const int SMEM_L1 = 2 * (128 * 68 * 4) + 2 * 768 + 32 * 68 * 4 + 128;  // 80000
    const int SMEM_L2 = 2 * (64 * 68 * 4)  + 2 * 768 + 32 * 68 * 4 + 128;  // 45184
    cudaFuncSetAttribute(aggW_k<128>, cudaFuncAttributeMaxDynamicSharedMemorySize, SMEM_L1);
    cudaFuncSetAttribute(aggW_k<64>,  cudaFuncAttributeMaxDynamicSharedMemorySize, SMEM_L2);

    // Layer 1 (launch order arranged so aggW_k<128> is the 4th launch -> ncu profiles it)
    gemm_k<64, 64, 4, 4, 0><<<dim3(64, 2, 4), 256>>>(x, W_in, 128, 128);          // 1
    scores_pack_k<<<2048 + 2048, 256>>>(a_in, 128, NHEADS * NNODES, adj, 2048);   // 2
    transpose_tf32_k<128><<<dim3(128, 4, 4), 256>>>();                            // 3
    aggW_k<128><<<dim3(128, 4), 256, SMEM_L1>>>(x);                               // 4

    // Layer 2
    gemm_k<64, 64, 4, 4, 1><<<dim3(64, 1, 4), 256>>>(nullptr, W_hid, 512, 64);
    scores_k<<<(NHEADS * NNODES) / 8, 256>>>(a_hid, 64, NHEADS * NNODES);
    transpose_tf32_k<64><<<dim3(128, 2, 4), 256>>>();
    aggW_k<64><<<dim3(128, 4), 128, SMEM_L2>>>(nullptr);

    // Layer 3
    gemm_k<64, 16, 4, 1, 2><<<dim3(64, 1, 1), 256>>>(nullptr, W_out, 256, 16);
    scores_k<<<NNODES / 8, 256>>>(a_out, 16, NNODES);
    agg3_k<<<dim3(128, 1, 1), 128>>>();

    logsoftmax_k<<<NNODES / 8, 256>>>(out);
}

// round 13
// speedup vs baseline: 1.0641x; 1.0641x over previous
#include <cuda_runtime.h>
#include <cuda_bf16.h>
#include <cstdint>
#include <math.h>

#define NNODES 4096
#define NW 128
#define NHEADS 4

typedef unsigned long long ull;

// ---------------- scratch ----------------
__device__ unsigned g_adjbits[NNODES * NW];
__device__ float g_hf[NHEADS * NNODES * 128];
__device__ float g_f1[NHEADS * NNODES];
__device__ float g_f2[NHEADS * NNODES];
__device__ float g_E1[NHEADS * NNODES];
__device__ float g_E1s[NHEADS * NNODES];
__device__ float g_E2[NHEADS * NNODES];
__device__ float g_E2s[NHEADS * NNODES];
__device__ float g_cat1[NNODES * 512];
__device__ float g_cat2[NNODES * 256];
__device__ float g_h3[NNODES * 16];
__device__ float g_hT[NHEADS * 128 * NNODES];  // [h][d][m'], tf32, m pair-permuted

__device__ __forceinline__ float eluf(float v) { return v > 0.f ? v : expm1f(v); }

__device__ __forceinline__ uint32_t smem_u32(const void* p) {
    uint32_t a;
    asm("{ .reg .u64 t; cvta.to.shared.u64 t, %1; cvt.u32.u64 %0, t; }" : "=r"(a) : "l"(p));
    return a;
}
__device__ __forceinline__ uint32_t tf32u(float v) {
    uint32_t r;
    asm("cvt.rna.tf32.f32 %0, %1;" : "=r"(r) : "f"(v));
    return r;
}

#define CP16(dst, src) \
    asm volatile("cp.async.cg.shared.global [%0], [%1], 16;" :: "r"(dst), "l"(src))
#define CP_COMMIT() asm volatile("cp.async.commit_group;" ::: "memory")
#define CP_WAIT(n)  asm volatile("cp.async.wait_group %0;" :: "n"(n) : "memory")

__device__ __forceinline__ void mma_tf32(float* c, uint32_t a0, uint32_t a1,
                                         uint32_t a2, uint32_t a3,
                                         uint32_t b0, uint32_t b1) {
    asm volatile(
        "mma.sync.aligned.m16n8k8.row.col.f32.tf32.tf32.f32 "
        "{%0,%1,%2,%3}, {%4,%5,%6,%7}, {%8,%9}, {%0,%1,%2,%3};"
        : "+f"(c[0]), "+f"(c[1]), "+f"(c[2]), "+f"(c[3])
        : "r"(a0), "r"(a1), "r"(a2), "r"(a3), "r"(b0), "r"(b1));
}

// ---------------- feature GEMM ----------------
template<int TN, int TD, int MR, int NC, int SRC>
__global__ __launch_bounds__(256) void gemm_k(const float* __restrict__ Aext,
                                              const float* __restrict__ W,
                                              int K, int Dtot) {
    const int TK = 16;
    __shared__ float As[TK][TN];
    __shared__ float Bs[TK][TD];
    const float* A = (SRC == 0) ? Aext : (SRC == 1 ? g_cat1 : g_cat2);

    int t = threadIdx.x;
    int n0 = blockIdx.x * TN;
    int d0 = blockIdx.y * TD;
    int h  = blockIdx.z;
    const float* Wh = W + (size_t)h * K * Dtot;
    const int rg = t / (TD / NC);
    const int cg = t % (TD / NC);

    float acc[MR][NC];
#pragma unroll
    for (int i = 0; i < MR; i++)
#pragma unroll
        for (int j = 0; j < NC; j++) acc[i][j] = 0.f;

    for (int k0 = 0; k0 < K; k0 += TK) {
        for (int idx = t; idx < TN * (TK / 4); idx += 256) {
            int i_n = idx / (TK / 4);
            int k4  = idx % (TK / 4);
            float4 v = *(const float4*)&A[(size_t)(n0 + i_n) * K + k0 + 4 * k4];
            As[4 * k4 + 0][i_n] = v.x;
            As[4 * k4 + 1][i_n] = v.y;
            As[4 * k4 + 2][i_n] = v.z;
            As[4 * k4 + 3][i_n] = v.w;
        }
        for (int idx = t; idx < TK * (TD / 4); idx += 256) {
            int kk = idx / (TD / 4);
            int j4 = idx % (TD / 4);
            *(float4*)&Bs[kk][4 * j4] =
                *(const float4*)&Wh[(size_t)(k0 + kk) * Dtot + d0 + 4 * j4];
        }
        __syncthreads();
#pragma unroll
        for (int k = 0; k < TK; k++) {
            float a_[MR], b_[NC];
#pragma unroll
            for (int i = 0; i < MR; i++) a_[i] = As[k][rg * MR + i];
#pragma unroll
            for (int j = 0; j < NC; j++) b_[j] = Bs[k][cg * NC + j];
#pragma unroll
            for (int i = 0; i < MR; i++)
#pragma unroll
                for (int j = 0; j < NC; j++)
                    acc[i][j] = fmaf(a_[i], b_[j], acc[i][j]);
        }
        __syncthreads();
    }
    float* Ch = g_hf + (size_t)h * NNODES * Dtot;
#pragma unroll
    for (int i = 0; i < MR; i++)
#pragma unroll
        for (int j = 0; j < NC; j++)
            Ch[(size_t)(n0 + rg * MR + i) * Dtot + d0 + cg * NC + j] = acc[i][j];
}

// ---------------- scores (optionally fused with adjacency bit-pack) ----------------
__device__ __forceinline__ void scores_body(const float* a, int D, int total,
                                            int blk, int t) {
    int gid  = blk * 8 + (t >> 5);
    int lane = t & 31;
    if (gid >= total) return;
    int h = gid / NNODES, n = gid % NNODES;
    const float* hr = g_hf + ((size_t)h * NNODES + n) * D;
    const float* a1 = a + (size_t)h * 2 * D;
    const float* a2 = a1 + D;
    float s1 = 0.f, s2 = 0.f;
    for (int d = lane; d < D; d += 32) {
        float v = hr[d];
        s1 += v * a1[d];
        s2 += v * a2[d];
    }
#pragma unroll
    for (int o = 16; o; o >>= 1) {
        s1 += __shfl_xor_sync(~0u, s1, o);
        s2 += __shfl_xor_sync(~0u, s2, o);
    }
    if (!lane) {
        int idx = h * NNODES + n;
        g_f1[idx]  = s1;
        g_f2[idx]  = s2;
        g_E1[idx]  = expf(s1);
        g_E1s[idx] = expf(0.2f * s1);
        g_E2[idx]  = expf(s2);
        g_E2s[idx] = expf(0.2f * s2);
    }
}

__global__ __launch_bounds__(256) void scores_k(const float* __restrict__ a, int D, int total) {
    scores_body(a, D, total, blockIdx.x, threadIdx.x);
}

__global__ __launch_bounds__(256) void scores_pack_k(const float* __restrict__ a, int D,
                                                     int total, const int* __restrict__ adj,
                                                     int scoreBlocks) {
    if ((int)blockIdx.x < scoreBlocks) {
        scores_body(a, D, total, blockIdx.x, threadIdx.x);
        return;
    }
    int wi = (blockIdx.x - scoreBlocks) * 256 + threadIdx.x;
    if (wi >= NNODES * NW) return;
    const int4* p = (const int4*)adj + (size_t)wi * 8;
    unsigned w = 0;
#pragma unroll
    for (int q = 0; q < 8; q++) {
        int4 v = p[q];
        if (v.x > 0) w |= 1u << (q * 4 + 0);
        if (v.y > 0) w |= 1u << (q * 4 + 1);
        if (v.z > 0) w |= 1u << (q * 4 + 2);
        if (v.w > 0) w |= 1u << (q * 4 + 3);
    }
    g_adjbits[wi] = w;
}

// ---------------- transpose + tf32 + m-pair-permute: g_hf[h][n][d] -> g_hT[h][d][m'] ----
// m' = (m & ~7) + 2*(m&3) + ((m>>2)&1)  so mma fragment pairs (m, m+4) are adjacent.
template<int D>
__global__ __launch_bounds__(256) void transpose_tf32_k() {
    __shared__ float ts[32][33];
    int t  = threadIdx.x;
    int nt = blockIdx.x, dt = blockIdx.y, h = blockIdx.z;
    int r0 = t / 32, c = t % 32;
#pragma unroll
    for (int p = 0; p < 4; p++) {
        int r = p * 8 + r0;
        ts[r][c] = g_hf[((size_t)h * NNODES + nt * 32 + r) * D + dt * 32 + c];
    }
    __syncthreads();
    const int cperm = (c & ~7) + 2 * (c & 3) + ((c >> 2) & 1);
#pragma unroll
    for (int p = 0; p < 4; p++) {
        int dr = p * 8 + r0;
        uint32_t v = tf32u(ts[c][dr]);
        size_t addr = ((size_t)h * D + dt * 32 + dr) * NNODES + nt * 32 + cperm;
        g_hT[addr] = __uint_as_float(v);
    }
}

// ---------------- tf32 mma aggregation v3: 32x32 warp tiles, paired LDS.64 ----
// CTA: 64 n-rows x D cols. WARPS warps, each 32r x 32c (2 Mg x 4 n8-tiles).
// L1: D=128, 8 warps; L2: D=64, 4 warps. Chunk = 32 m, double-buffered cp.async.
// Weights computed once/CTA into Wsm (pair-permuted cols), consumed as LDS.64 frags.
template<int D, int WARPS>
__global__ __launch_bounds__(WARPS * 32, (WARPS == 8) ? 3 : 6)
void aggW2_k(const float* __restrict__ resid) {
    constexpr int TB   = WARPS * 32;
    constexpr int NCG  = D / 32;
    constexpr int NCH  = NNODES / 32;
    constexpr int BST  = 40;                  // floats per row (32 + 8 pad; ≡8 mod 32)
    constexpr int BBUF = D * BST * 4;
    constexpr int O_W  = 2 * BBUF;
    constexpr int O_E  = O_W + 64 * BST * 4;
    constexpr int O_Z  = O_E + 2 * 512;
    constexpr int R    = 256 / TB;            // row-passes per thread (1 or 2)
    constexpr int RPP  = TB / 4;              // rows per pass

    extern __shared__ __align__(16) char sm[];
    const uint32_t sb = smem_u32(sm);
    float* Wp = (float*)(sm + O_W);
    float* Zs = (float*)(sm + O_Z);

    const int t = threadIdx.x, lane = t & 31, wid = t >> 5;
    const int cg = wid % NCG, rg = wid / NCG;      // rg in {0,1}
    const int n0 = blockIdx.x * 64;
    const int head = blockIdx.y;
    const int headN = head * NNODES;
    const int rq  = lane >> 2;
    const int k0b = lane & 3;
    const int i4  = t & 3;
    const int wr0 = t >> 2;

    // weight-thread row constants
    float f1r[R], E1r[R], E1sr[R];
    const unsigned* adjp[R];
#pragma unroll
    for (int r = 0; r < R; r++) {
        int row = wr0 + r * RPP;
        f1r[r]  = g_f1[headN + n0 + row];
        E1r[r]  = g_E1[headN + n0 + row];
        E1sr[r] = g_E1s[headN + n0 + row];
        adjp[r] = g_adjbits + (size_t)(n0 + row) * NW;
    }
    float zacc[R];
#pragma unroll
    for (int r = 0; r < R; r++) zacc[r] = 0.f;

    float acc[2][4][4];
#pragma unroll
    for (int mg = 0; mg < 2; mg++)
#pragma unroll
        for (int ng = 0; ng < 4; ng++)
#pragma unroll
            for (int q = 0; q < 4; q++) acc[mg][ng][q] = 0.f;

    auto fill = [&](int chunk, int buf) {
        for (int idx = t; idx < D * 8; idx += TB) {
            int row = idx >> 3, c8 = idx & 7;
            uint32_t dst = sb + (uint32_t)(buf * BBUF + (row * BST + c8 * 4) * 4);
            size_t s = ((size_t)(head * D + row)) * NNODES + chunk * 32 + c8 * 4;
            CP16(dst, (const void*)(g_hT + s));
        }
        if (t < 24) {
            int a = t >> 3, q = t & 7;
            const float* s = (a == 0 ? g_f2 : a == 1 ? g_E2 : g_E2s) +
                             headN + chunk * 32 + q * 4;
            uint32_t dst = sb + (uint32_t)(O_E + buf * 512 + a * 128 + q * 16);
            CP16(dst, (const void*)s);
        }
    };

    unsigned mcur[R], mnext[R];
#pragma unroll
    for (int r = 0; r < R; r++) mcur[r] = adjp[r][0];

    fill(0, 0); CP_COMMIT();

    for (int c = 0; c < NCH; c++) {
        const int buf = c & 1;
        CP_WAIT(0);
        __syncthreads();                     // fill(c) visible; chunk c-1 readers done
        if (c + 1 < NCH) { fill(c + 1, buf ^ 1); CP_COMMIT(); }
#pragma unroll
        for (int r = 0; r < R; r++)
            mnext[r] = (c + 1 < NCH) ? adjp[r][c + 1] : 0u;

        // ---- weights: thread owns m ≡ i4 (mod 4) in rows wr0 (+RPP) ----
        {
            const float* f2c  = (const float*)(sm + O_E + buf * 512);
            const float* E2c  = f2c + 32;
            const float* E2sc = f2c + 64;
#pragma unroll
            for (int r = 0; r < R; r++) {
                float* wrow = Wp + (wr0 + r * RPP) * BST;
                unsigned mw = mcur[r];
#pragma unroll
                for (int blk = 0; blk < 4; blk++)
#pragma unroll
                    for (int half = 0; half < 2; half++) {
                        int m = blk * 8 + half * 4 + i4;
                        float s = f1r[r] + f2c[m];
                        float w = (s >= 0.f) ? E1r[r] * E2c[m] : E1sr[r] * E2sc[m];
                        w = ((mw >> m) & 1u) ? w : 0.f;
                        zacc[r] += w;
                        wrow[blk * 8 + 2 * i4 + half] = __uint_as_float(tf32u(w));
                    }
            }
        }
        __syncthreads();                     // W visible

        // ---- mma: 4 k-steps, paired LDS.64 fragments ----
        const float* Bs = (const float*)(sm + buf * BBUF);
#pragma unroll
        for (int ks = 0; ks < 4; ks++) {
            const int cw = ks * 8 + 2 * k0b;
            uint2 a0[2], a1[2];
#pragma unroll
            for (int mg = 0; mg < 2; mg++) {
                const float* w0 = Wp + (rg * 32 + mg * 16 + rq) * BST + cw;
                a0[mg] = *(const uint2*)w0;             // (m, m+4) for row rq
                a1[mg] = *(const uint2*)(w0 + 8 * BST); // row rq+8
            }
#pragma unroll
            for (int ng = 0; ng < 4; ng++) {
                const float* bp = Bs + (cg * 32 + ng * 8 + rq) * BST + cw;
                uint2 b = *(const uint2*)bp;
#pragma unroll
                for (int mg = 0; mg < 2; mg++)
                    mma_tf32(acc[mg][ng], a0[mg].x, a1[mg].x, a0[mg].y, a1[mg].y,
                             b.x, b.y);
            }
        }
#pragma unroll
        for (int r = 0; r < R; r++) mcur[r] = mnext[r];
    }

    // ---- Z: reduce over quad (4 threads per row) ----
#pragma unroll
    for (int r = 0; r < R; r++) {
        float z = zacc[r];
        z += __shfl_xor_sync(~0u, z, 1);
        z += __shfl_xor_sync(~0u, z, 2);
        if (i4 == 0) Zs[wr0 + r * RPP] = 1.f / z;
    }
    __syncthreads();

    float* out = (D == 128) ? g_cat1 : g_cat2;
    const int ostr = (D == 128) ? 512 : 256;
#pragma unroll
    for (int mg = 0; mg < 2; mg++) {
        int lr = rg * 32 + mg * 16 + rq;
        float zi0 = Zs[lr], zi1 = Zs[lr + 8];
        int n = n0 + lr;
#pragma unroll
        for (int ng = 0; ng < 4; ng++) {
            int col = cg * 32 + ng * 8 + (lane & 3) * 2;
            float v0 = acc[mg][ng][0] * zi0, v1 = acc[mg][ng][1] * zi0;
            float v2 = acc[mg][ng][2] * zi1, v3 = acc[mg][ng][3] * zi1;
            if (D == 128) {
                float2 ra = *(const float2*)&resid[(size_t)n * 128 + col];
                float2 rb = *(const float2*)&resid[(size_t)(n + 8) * 128 + col];
                v0 += ra.x; v1 += ra.y; v2 += rb.x; v3 += rb.y;
            }
            float2 o0 = {eluf(v0), eluf(v1)};
            float2 o1 = {eluf(v2), eluf(v3)};
            *(float2*)&out[(size_t)n * ostr + head * D + col]       = o0;
            *(float2*)&out[(size_t)(n + 8) * ostr + head * D + col] = o1;
        }
    }
}

// ---------------- SIMT agg for layer 3 (D=16) ----------------
__device__ __forceinline__ ull dupf(float v) {
    ull r; asm("mov.b64 %0, {%1, %1};" : "=l"(r) : "f"(v)); return r;
}
__device__ __forceinline__ void ffma2(ull& acc, ull a, ull b) {
    asm("fma.rn.f32x2 %0, %1, %2, %0;" : "+l"(acc) : "l"(a), "l"(b));
}
__device__ __forceinline__ float2 unpack2(ull v) {
    float2 r; asm("mov.b64 {%0, %1}, %2;" : "=f"(r.x), "=f"(r.y) : "l"(v)); return r;
}

__global__ __launch_bounds__(128) void agg3_k() {
    const int D = 16, TN = 32, TM = 32, MR = 2, NC = 2;
    __shared__ __align__(16) float hs[2][TM][D];
    __shared__ __align__(16) float ws[2][TM][TN + 2];
    __shared__ float Zred[128];
    __shared__ float Zs[TN];

    const int t  = threadIdx.x;
    const int n0 = blockIdx.x * TN;
    const float* hfh = g_hf;

    const int rA = t % TN;
    const int G  = 128 / TN;
    const int g  = t / TN;
    const int MMPT = TM / G;

    const float rf1  = g_f1[n0 + rA];
    const float rE1  = g_E1[n0 + rA];
    const float rE1s = g_E1s[n0 + rA];
    float zacc = 0.f;

    const int rg = t / (D / NC);
    const int cg = t % (D / NC);

    ull acc[NC];
#pragma unroll
    for (int j = 0; j < NC; j++) acc[j] = 0ull;

    auto fill = [&](int wti, int buf) {
        int m0 = wti * TM;
        for (int idx = t; idx < TM * (D / 4); idx += 128) {
            int m  = idx / (D / 4);
            int dd = idx % (D / 4);
            *(float4*)&hs[buf][m][4 * dd] = *(const float4*)&hfh[(size_t)(m0 + m) * D + 4 * dd];
        }
        unsigned aw = g_adjbits[(size_t)(n0 + rA) * NW + wti];
#pragma unroll
        for (int j = 0; j < MMPT; j++) {
            int mm = g + G * j;
            float w = 0.f;
            if ((aw >> mm) & 1u) {
                float s = rf1 + g_f2[m0 + mm];
                w = (s >= 0.f) ? rE1 * g_E2[m0 + mm] : rE1s * g_E2s[m0 + mm];
            }
            ws[buf][mm][rA] = w;
            zacc += w;
        }
    };

    fill(0, 0);
    __syncthreads();
    const int NT = NNODES / TM;
    for (int mt = 0; mt < NT; mt++) {
        int cur = mt & 1;
        if (mt + 1 < NT) fill(mt + 1, cur ^ 1);
#pragma unroll
        for (int k = 0; k < TM; k++) {
            ull a2 = *(const ull*)&ws[cur][k][rg * MR];
#pragma unroll
            for (int j = 0; j < NC; j++) {
                ull bb = dupf(hs[cur][k][cg * NC + j]);
                ffma2(acc[j], a2, bb);
            }
        }
        __syncthreads();
    }
    Zred[t] = zacc;
    __syncthreads();
    if (t < TN) {
        float z = 0.f;
#pragma unroll
        for (int q = 0; q < G; q++) z += Zred[t + q * TN];
        Zs[t] = 1.f / z;
    }
    __syncthreads();
    {
        int lr0 = rg * MR;
        float zi0 = Zs[lr0], zi1 = Zs[lr0 + 1];
#pragma unroll
        for (int j = 0; j < NC; j++) {
            float2 v = unpack2(acc[j]);
            int d = cg * NC + j;
            g_h3[(size_t)(n0 + lr0) * 16 + d]     = eluf(v.x * zi0);
            g_h3[(size_t)(n0 + lr0 + 1) * 16 + d] = eluf(v.y * zi1);
        }
    }
}

// ---------------- final log-softmax ----------------
__global__ __launch_bounds__(256) void logsoftmax_k(float* __restrict__ out) {
    int n    = blockIdx.x * 8 + (threadIdx.x >> 5);
    int lane = threadIdx.x & 31;
    if (n >= NNODES) return;
    float v = (lane < 16) ? g_h3[n * 16 + lane] : -INFINITY;
    float m = v;
#pragma unroll
    for (int o = 16; o; o >>= 1) m = fmaxf(m, __shfl_xor_sync(~0u, m, o));
    float e = (lane < 16) ? expf(v - m) : 0.f;
    float s = e;
#pragma unroll
    for (int o = 16; o; o >>= 1) s += __shfl_xor_sync(~0u, s, o);
    if (lane < 16) out[n * 16 + lane] = v - m - logf(s);
}

// ---------------- launch ----------------
extern "C" void kernel_launch(void* const* d_in, const int* in_sizes, int n_in,
                              void* d_out, int out_size) {
    const float* x     = (const float*)d_in[0];
    const int*   adj   = (const int*)d_in[1];
    const float* W_in  = (const float*)d_in[2];
    const float* a_in  = (const float*)d_in[3];
    const float* W_hid = (const float*)d_in[4];
    const float* a_hid = (const float*)d_in[5];
    const float* W_out = (const float*)d_in[6];
    const float* a_out = (const float*)d_in[7];
    float* out = (float*)d_out;

    // smem: 2*B + W + E + Z
    const int SMEM_L1 = 2 * (128 * 40 * 4) + 64 * 40 * 4 + 2 * 512 + 256 + 64;  // ~52.5KB
    const int SMEM_L2 = 2 * (64 * 40 * 4)  + 64 * 40 * 4 + 2 * 512 + 256 + 64;  // ~32KB
    cudaFuncSetAttribute(aggW2_k<128, 8>, cudaFuncAttributeMaxDynamicSharedMemorySize, SMEM_L1);
    cudaFuncSetAttribute(aggW2_k<64, 4>,  cudaFuncAttributeMaxDynamicSharedMemorySize, SMEM_L2);

    // Layer 1 (aggW2_k<128,8> is launch #4 -> ncu profiles it)
    gemm_k<64, 64, 4, 4, 0><<<dim3(64, 2, 4), 256>>>(x, W_in, 128, 128);          // 1
    scores_pack_k<<<2048 + 2048, 256>>>(a_in, 128, NHEADS * NNODES, adj, 2048);   // 2
    transpose_tf32_k<128><<<dim3(128, 4, 4), 256>>>();                            // 3
    aggW2_k<128, 8><<<dim3(64, 4), 256, SMEM_L1>>>(x);                            // 4

    // Layer 2
    gemm_k<64, 64, 4, 4, 1><<<dim3(64, 1, 4), 256>>>(nullptr, W_hid, 512, 64);
    scores_k<<<(NHEADS * NNODES) / 8, 256>>>(a_hid, 64, NHEADS * NNODES);
    transpose_tf32_k<64><<<dim3(128, 2, 4), 256>>>();
    aggW2_k<64, 4><<<dim3(64, 4), 128, SMEM_L2>>>(nullptr);

    // Layer 3
    gemm_k<64, 16, 4, 1, 2><<<dim3(64, 1, 1), 256>>>(nullptr, W_out, 256, 16);
    scores_k<<<NNODES / 8, 256>>>(a_out, 16, NNODES);
    agg3_k<<<dim3(128, 1, 1), 128>>>();

    logsoftmax_k<<<NNODES / 8, 256>>>(out);
}

// round 14
// speedup vs baseline: 1.1695x; 1.0991x over previous
#include <cuda_runtime.h>
#include <cuda_bf16.h>
#include <cstdint>
#include <math.h>

#define NNODES 4096
#define NW 128
#define NHEADS 4

typedef unsigned long long ull;

// ---------------- scratch ----------------
__device__ unsigned g_adjbits[NNODES * NW];
__device__ float g_hf[NHEADS * NNODES * 128];
__device__ float g_f1[NHEADS * NNODES];
__device__ float g_f2[NHEADS * NNODES];
__device__ float g_E1[NHEADS * NNODES];
__device__ float g_E1s[NHEADS * NNODES];
__device__ float g_E2[NHEADS * NNODES];
__device__ float g_E2s[NHEADS * NNODES];
__device__ float2 g_E2p[NHEADS * NNODES];      // (E2, E2s) interleaved
__device__ float g_cat1[NNODES * 512];
__device__ float g_cat2[NNODES * 256];
__device__ float g_h3[NNODES * 16];
__device__ float g_hT[NHEADS * 128 * NNODES];  // [h][d][m'], tf32, m pair-permuted

__device__ __forceinline__ float eluf(float v) { return v > 0.f ? v : expm1f(v); }

__device__ __forceinline__ uint32_t smem_u32(const void* p) {
    uint32_t a;
    asm("{ .reg .u64 t; cvta.to.shared.u64 t, %1; cvt.u32.u64 %0, t; }" : "=r"(a) : "l"(p));
    return a;
}
__device__ __forceinline__ uint32_t tf32u(float v) {
    uint32_t r;
    asm("cvt.rna.tf32.f32 %0, %1;" : "=r"(r) : "f"(v));
    return r;
}

#define CP16(dst, src) \
    asm volatile("cp.async.cg.shared.global [%0], [%1], 16;" :: "r"(dst), "l"(src))
#define CP_COMMIT() asm volatile("cp.async.commit_group;" ::: "memory")
#define CP_WAIT(n)  asm volatile("cp.async.wait_group %0;" :: "n"(n) : "memory")

__device__ __forceinline__ void mma_tf32(float* c, uint32_t a0, uint32_t a1,
                                         uint32_t a2, uint32_t a3,
                                         uint32_t b0, uint32_t b1) {
    asm volatile(
        "mma.sync.aligned.m16n8k8.row.col.f32.tf32.tf32.f32 "
        "{%0,%1,%2,%3}, {%4,%5,%6,%7}, {%8,%9}, {%0,%1,%2,%3};"
        : "+f"(c[0]), "+f"(c[1]), "+f"(c[2]), "+f"(c[3])
        : "r"(a0), "r"(a1), "r"(a2), "r"(a3), "r"(b0), "r"(b1));
}

// ---------------- feature GEMM ----------------
template<int TN, int TD, int MR, int NC, int SRC>
__global__ __launch_bounds__(256) void gemm_k(const float* __restrict__ Aext,
                                              const float* __restrict__ W,
                                              int K, int Dtot) {
    const int TK = 16;
    __shared__ float As[TK][TN];
    __shared__ float Bs[TK][TD];
    const float* A = (SRC == 0) ? Aext : (SRC == 1 ? g_cat1 : g_cat2);

    int t = threadIdx.x;
    int n0 = blockIdx.x * TN;
    int d0 = blockIdx.y * TD;
    int h  = blockIdx.z;
    const float* Wh = W + (size_t)h * K * Dtot;
    const int rg = t / (TD / NC);
    const int cg = t % (TD / NC);

    float acc[MR][NC];
#pragma unroll
    for (int i = 0; i < MR; i++)
#pragma unroll
        for (int j = 0; j < NC; j++) acc[i][j] = 0.f;

    for (int k0 = 0; k0 < K; k0 += TK) {
        for (int idx = t; idx < TN * (TK / 4); idx += 256) {
            int i_n = idx / (TK / 4);
            int k4  = idx % (TK / 4);
            float4 v = *(const float4*)&A[(size_t)(n0 + i_n) * K + k0 + 4 * k4];
            As[4 * k4 + 0][i_n] = v.x;
            As[4 * k4 + 1][i_n] = v.y;
            As[4 * k4 + 2][i_n] = v.z;
            As[4 * k4 + 3][i_n] = v.w;
        }
        for (int idx = t; idx < TK * (TD / 4); idx += 256) {
            int kk = idx / (TD / 4);
            int j4 = idx % (TD / 4);
            *(float4*)&Bs[kk][4 * j4] =
                *(const float4*)&Wh[(size_t)(k0 + kk) * Dtot + d0 + 4 * j4];
        }
        __syncthreads();
#pragma unroll
        for (int k = 0; k < TK; k++) {
            float a_[MR], b_[NC];
#pragma unroll
            for (int i = 0; i < MR; i++) a_[i] = As[k][rg * MR + i];
#pragma unroll
            for (int j = 0; j < NC; j++) b_[j] = Bs[k][cg * NC + j];
#pragma unroll
            for (int i = 0; i < MR; i++)
#pragma unroll
                for (int j = 0; j < NC; j++)
                    acc[i][j] = fmaf(a_[i], b_[j], acc[i][j]);
        }
        __syncthreads();
    }
    float* Ch = g_hf + (size_t)h * NNODES * Dtot;
#pragma unroll
    for (int i = 0; i < MR; i++)
#pragma unroll
        for (int j = 0; j < NC; j++)
            Ch[(size_t)(n0 + rg * MR + i) * Dtot + d0 + cg * NC + j] = acc[i][j];
}

// ---------------- scores (optionally fused with adjacency bit-pack) ----------------
__device__ __forceinline__ void scores_body(const float* a, int D, int total,
                                            int blk, int t) {
    int gid  = blk * 8 + (t >> 5);
    int lane = t & 31;
    if (gid >= total) return;
    int h = gid / NNODES, n = gid % NNODES;
    const float* hr = g_hf + ((size_t)h * NNODES + n) * D;
    const float* a1 = a + (size_t)h * 2 * D;
    const float* a2 = a1 + D;
    float s1 = 0.f, s2 = 0.f;
    for (int d = lane; d < D; d += 32) {
        float v = hr[d];
        s1 += v * a1[d];
        s2 += v * a2[d];
    }
#pragma unroll
    for (int o = 16; o; o >>= 1) {
        s1 += __shfl_xor_sync(~0u, s1, o);
        s2 += __shfl_xor_sync(~0u, s2, o);
    }
    if (!lane) {
        int idx = h * NNODES + n;
        float e2  = expf(s2);
        float e2s = expf(0.2f * s2);
        g_f1[idx]  = s1;
        g_f2[idx]  = s2;
        g_E1[idx]  = expf(s1);
        g_E1s[idx] = expf(0.2f * s1);
        g_E2[idx]  = e2;
        g_E2s[idx] = e2s;
        g_E2p[idx] = make_float2(e2, e2s);
    }
}

__global__ __launch_bounds__(256) void scores_k(const float* __restrict__ a, int D, int total) {
    scores_body(a, D, total, blockIdx.x, threadIdx.x);
}

__global__ __launch_bounds__(256) void scores_pack_k(const float* __restrict__ a, int D,
                                                     int total, const int* __restrict__ adj,
                                                     int scoreBlocks) {
    if ((int)blockIdx.x < scoreBlocks) {
        scores_body(a, D, total, blockIdx.x, threadIdx.x);
        return;
    }
    int wi = (blockIdx.x - scoreBlocks) * 256 + threadIdx.x;
    if (wi >= NNODES * NW) return;
    const int4* p = (const int4*)adj + (size_t)wi * 8;
    unsigned w = 0;
#pragma unroll
    for (int q = 0; q < 8; q++) {
        int4 v = p[q];
        if (v.x > 0) w |= 1u << (q * 4 + 0);
        if (v.y > 0) w |= 1u << (q * 4 + 1);
        if (v.z > 0) w |= 1u << (q * 4 + 2);
        if (v.w > 0) w |= 1u << (q * 4 + 3);
    }
    g_adjbits[wi] = w;
}

// ---------------- transpose + tf32 + m-pair-permute ----------------
// m' = (m & ~7) + 2*(m&3) + ((m>>2)&1)  so mma fragment pairs (m, m+4) are adjacent.
template<int D>
__global__ __launch_bounds__(256) void transpose_tf32_k() {
    __shared__ float ts[32][33];
    int t  = threadIdx.x;
    int nt = blockIdx.x, dt = blockIdx.y, h = blockIdx.z;
    int r0 = t / 32, c = t % 32;
#pragma unroll
    for (int p = 0; p < 4; p++) {
        int r = p * 8 + r0;
        ts[r][c] = g_hf[((size_t)h * NNODES + nt * 32 + r) * D + dt * 32 + c];
    }
    __syncthreads();
    const int cperm = (c & ~7) + 2 * (c & 3) + ((c >> 2) & 1);
#pragma unroll
    for (int p = 0; p < 4; p++) {
        int dr = p * 8 + r0;
        uint32_t v = tf32u(ts[c][dr]);
        size_t addr = ((size_t)h * D + dt * 32 + dr) * NNODES + nt * 32 + cperm;
        g_hT[addr] = __uint_as_float(v);
    }
}

// ---------------- tf32 mma aggregation v4: pipelined weights, 1 barrier/chunk ----
// CTA: ROWS n-rows x D cols, 256 threads (8 warps). Warp tile 32x32.
// L1: D=128, ROWS=64 (rg 0..1, cg 0..3). L2: D=64, ROWS=128 (rg 0..3, cg 0..1).
// Chunk=32 m. B/E: 4-slot cp.async ring. W: double buffer, computed 1 chunk ahead.
template<int D, int ROWS>
__global__ __launch_bounds__(256)
void aggW3_k(const float* __restrict__ resid) {
    constexpr int NCG  = D / 32;
    constexpr int NCH  = NNODES / 32;
    constexpr int BST  = 40;                   // floats per B/W row
    constexpr int BBUF = D * BST * 4;          // bytes per B slot
    constexpr int WBUF = ROWS * BST * 4;       // bytes per W buffer
    constexpr int O_W  = 4 * BBUF;
    constexpr int O_E  = O_W + 2 * WBUF;
    constexpr int ESL  = 384;                  // f2[32] + e2p[32] per slot
    constexpr int O_Z  = O_E + 4 * ESL;
    constexpr int R    = ROWS / 64;            // weight rows per thread

    extern __shared__ __align__(16) char sm[];
    const uint32_t sb = smem_u32(sm);
    float* Zs = (float*)(sm + O_Z);

    const int t = threadIdx.x, lane = t & 31, wid = t >> 5;
    const int cg = wid % NCG, rg = wid / NCG;
    const int n0 = blockIdx.x * ROWS;
    const int head = blockIdx.y;
    const int headN = head * NNODES;
    const int rq  = lane >> 2;
    const int k0b = lane & 3;
    const int i4  = t & 3;
    const int wr0 = t >> 2;                    // weight row (0..63), +64 if R=2

    float f1r[R], E1r[R], E1sr[R];
    const unsigned* adjp[R];
#pragma unroll
    for (int r = 0; r < R; r++) {
        int row = wr0 + r * 64;
        f1r[r]  = g_f1[headN + n0 + row];
        E1r[r]  = g_E1[headN + n0 + row];
        E1sr[r] = g_E1s[headN + n0 + row];
        adjp[r] = g_adjbits + (size_t)(n0 + row) * NW;
    }
    float zacc[R];
#pragma unroll
    for (int r = 0; r < R; r++) zacc[r] = 0.f;

    float acc[2][4][4];
#pragma unroll
    for (int mg = 0; mg < 2; mg++)
#pragma unroll
        for (int ng = 0; ng < 4; ng++)
#pragma unroll
            for (int q = 0; q < 4; q++) acc[mg][ng][q] = 0.f;

    auto fill = [&](int chunk) {
        const int slot = chunk & 3;
        for (int idx = t; idx < D * 8; idx += 256) {
            int row = idx >> 3, c8 = idx & 7;
            uint32_t dst = sb + (uint32_t)(slot * BBUF + (row * BST + c8 * 4) * 4);
            size_t s = ((size_t)(head * D + row)) * NNODES + chunk * 32 + c8 * 4;
            CP16(dst, (const void*)(g_hT + s));
        }
        if (t < 8) {            // f2: 32 floats
            uint32_t dst = sb + (uint32_t)(O_E + slot * ESL + t * 16);
            CP16(dst, (const void*)(g_f2 + headN + chunk * 32 + t * 4));
        } else if (t < 24) {    // e2 pairs: 32 float2
            int q = t - 8;
            uint32_t dst = sb + (uint32_t)(O_E + slot * ESL + 128 + q * 16);
            CP16(dst, (const void*)(g_E2p + headN + chunk * 32 + q * 2));
        }
    };

    auto weights = [&](int chunk) {
        const int slot = chunk & 3;
        const float*  f2c = (const float*)(sm + O_E + slot * ESL);
        const float2* e2p = (const float2*)(sm + O_E + slot * ESL + 128);
        float* Wb = (float*)(sm + O_W + (chunk & 1) * WBUF);
#pragma unroll
        for (int r = 0; r < R; r++) {
            unsigned mw = adjp[r][chunk];
            float* wrow = Wb + (wr0 + r * 64) * BST;
            float zl = 0.f;
#pragma unroll
            for (int blk = 0; blk < 4; blk++) {
                float w2[2];
#pragma unroll
                for (int half = 0; half < 2; half++) {
                    int m = blk * 8 + half * 4 + i4;
                    float s = f1r[r] + f2c[m];
                    float2 ep = e2p[m];
                    bool pos = (s >= 0.f);
                    float w = (pos ? E1r[r] : E1sr[r]) * (pos ? ep.x : ep.y);
                    w = ((mw >> m) & 1u) ? w : 0.f;
                    zl += w;
                    w2[half] = __uint_as_float(tf32u(w));
                }
                *(float2*)&wrow[blk * 8 + 2 * i4] = make_float2(w2[0], w2[1]);
            }
            zacc[r] += zl;
        }
    };

    auto mmastep = [&](int chunk) {
        const float* Bs = (const float*)(sm + (chunk & 3) * BBUF);
        const float* Wb = (const float*)(sm + O_W + (chunk & 1) * WBUF);
#pragma unroll
        for (int ks = 0; ks < 4; ks++) {
            const int cw = ks * 8 + 2 * k0b;
            uint2 a0[2], a1[2];
#pragma unroll
            for (int mg = 0; mg < 2; mg++) {
                const float* w0 = Wb + (rg * 32 + mg * 16 + rq) * BST + cw;
                a0[mg] = *(const uint2*)w0;
                a1[mg] = *(const uint2*)(w0 + 8 * BST);
            }
#pragma unroll
            for (int ng = 0; ng < 4; ng++) {
                const float* bp = Bs + (cg * 32 + ng * 8 + rq) * BST + cw;
                uint2 b = *(const uint2*)bp;
#pragma unroll
                for (int mg = 0; mg < 2; mg++)
                    mma_tf32(acc[mg][ng], a0[mg].x, a1[mg].x, a0[mg].y, a1[mg].y,
                             b.x, b.y);
            }
        }
    };

    // prologue
    fill(0); CP_COMMIT();
    fill(1); CP_COMMIT();
    CP_WAIT(1);
    __syncthreads();
    weights(0);

    for (int c = 0; c < NCH; c++) {
        if (c + 2 < NCH) { fill(c + 2); CP_COMMIT(); CP_WAIT(1); }
        else             { CP_WAIT(0); }
        __syncthreads();            // W(c), B(c), E(c+1) visible; chunk c-1 readers done
        if (c + 1 < NCH) weights(c + 1);
        mmastep(c);
    }

    // Z reduce over quad (4 threads per row)
#pragma unroll
    for (int r = 0; r < R; r++) {
        float z = zacc[r];
        z += __shfl_xor_sync(~0u, z, 1);
        z += __shfl_xor_sync(~0u, z, 2);
        if (i4 == 0) Zs[wr0 + r * 64] = 1.f / z;
    }
    __syncthreads();

    float* out = (D == 128) ? g_cat1 : g_cat2;
    const int ostr = (D == 128) ? 512 : 256;
#pragma unroll
    for (int mg = 0; mg < 2; mg++) {
        int lr = rg * 32 + mg * 16 + rq;
        float zi0 = Zs[lr], zi1 = Zs[lr + 8];
        int n = n0 + lr;
#pragma unroll
        for (int ng = 0; ng < 4; ng++) {
            int col = cg * 32 + ng * 8 + (lane & 3) * 2;
            float v0 = acc[mg][ng][0] * zi0, v1 = acc[mg][ng][1] * zi0;
            float v2 = acc[mg][ng][2] * zi1, v3 = acc[mg][ng][3] * zi1;
            if (D == 128) {
                float2 ra = *(const float2*)&resid[(size_t)n * 128 + col];
                float2 rb = *(const float2*)&resid[(size_t)(n + 8) * 128 + col];
                v0 += ra.x; v1 += ra.y; v2 += rb.x; v3 += rb.y;
            }
            float2 o0 = {eluf(v0), eluf(v1)};
            float2 o1 = {eluf(v2), eluf(v3)};
            *(float2*)&out[(size_t)n * ostr + head * D + col]       = o0;
            *(float2*)&out[(size_t)(n + 8) * ostr + head * D + col] = o1;
        }
    }
}

// ---------------- SIMT agg for layer 3 (D=16) ----------------
__device__ __forceinline__ ull dupf(float v) {
    ull r; asm("mov.b64 %0, {%1, %1};" : "=l"(r) : "f"(v)); return r;
}
__device__ __forceinline__ void ffma2(ull& acc, ull a, ull b) {
    asm("fma.rn.f32x2 %0, %1, %2, %0;" : "+l"(acc) : "l"(a), "l"(b));
}
__device__ __forceinline__ float2 unpack2(ull v) {
    float2 r; asm("mov.b64 {%0, %1}, %2;" : "=f"(r.x), "=f"(r.y) : "l"(v)); return r;
}

__global__ __launch_bounds__(128) void agg3_k() {
    const int D = 16, TN = 32, TM = 32, MR = 2, NC = 2;
    __shared__ __align__(16) float hs[2][TM][D];
    __shared__ __align__(16) float ws[2][TM][TN + 2];
    __shared__ float Zred[128];
    __shared__ float Zs[TN];

    const int t  = threadIdx.x;
    const int n0 = blockIdx.x * TN;
    const float* hfh = g_hf;

    const int rA = t % TN;
    const int G  = 128 / TN;
    const int g  = t / TN;
    const int MMPT = TM / G;

    const float rf1  = g_f1[n0 + rA];
    const float rE1  = g_E1[n0 + rA];
    const float rE1s = g_E1s[n0 + rA];
    float zacc = 0.f;

    const int rg = t / (D / NC);
    const int cg = t % (D / NC);

    ull acc[NC];
#pragma unroll
    for (int j = 0; j < NC; j++) acc[j] = 0ull;

    auto fill = [&](int wti, int buf) {
        int m0 = wti * TM;
        for (int idx = t; idx < TM * (D / 4); idx += 128) {
            int m  = idx / (D / 4);
            int dd = idx % (D / 4);
            *(float4*)&hs[buf][m][4 * dd] = *(const float4*)&hfh[(size_t)(m0 + m) * D + 4 * dd];
        }
        unsigned aw = g_adjbits[(size_t)(n0 + rA) * NW + wti];
#pragma unroll
        for (int j = 0; j < MMPT; j++) {
            int mm = g + G * j;
            float w = 0.f;
            if ((aw >> mm) & 1u) {
                float s = rf1 + g_f2[m0 + mm];
                w = (s >= 0.f) ? rE1 * g_E2[m0 + mm] : rE1s * g_E2s[m0 + mm];
            }
            ws[buf][mm][rA] = w;
            zacc += w;
        }
    };

    fill(0, 0);
    __syncthreads();
    const int NT = NNODES / TM;
    for (int mt = 0; mt < NT; mt++) {
        int cur = mt & 1;
        if (mt + 1 < NT) fill(mt + 1, cur ^ 1);
#pragma unroll
        for (int k = 0; k < TM; k++) {
            ull a2 = *(const ull*)&ws[cur][k][rg * MR];
#pragma unroll
            for (int j = 0; j < NC; j++) {
                ull bb = dupf(hs[cur][k][cg * NC + j]);
                ffma2(acc[j], a2, bb);
            }
        }
        __syncthreads();
    }
    Zred[t] = zacc;
    __syncthreads();
    if (t < TN) {
        float z = 0.f;
#pragma unroll
        for (int q = 0; q < G; q++) z += Zred[t + q * TN];
        Zs[t] = 1.f / z;
    }
    __syncthreads();
    {
        int lr0 = rg * MR;
        float zi0 = Zs[lr0], zi1 = Zs[lr0 + 1];
#pragma unroll
        for (int j = 0; j < NC; j++) {
            float2 v = unpack2(acc[j]);
            int d = cg * NC + j;
            g_h3[(size_t)(n0 + lr0) * 16 + d]     = eluf(v.x * zi0);
            g_h3[(size_t)(n0 + lr0 + 1) * 16 + d] = eluf(v.y * zi1);
        }
    }
}

// ---------------- final log-softmax ----------------
__global__ __launch_bounds__(256) void logsoftmax_k(float* __restrict__ out) {
    int n    = blockIdx.x * 8 + (threadIdx.x >> 5);
    int lane = threadIdx.x & 31;
    if (n >= NNODES) return;
    float v = (lane < 16) ? g_h3[n * 16 + lane] : -INFINITY;
    float m = v;
#pragma unroll
    for (int o = 16; o; o >>= 1) m = fmaxf(m, __shfl_xor_sync(~0u, m, o));
    float e = (lane < 16) ? expf(v - m) : 0.f;
    float s = e;
#pragma unroll
    for (int o = 16; o; o >>= 1) s += __shfl_xor_sync(~0u, s, o);
    if (lane < 16) out[n * 16 + lane] = v - m - logf(s);
}

// ---------------- launch ----------------
extern "C" void kernel_launch(void* const* d_in, const int* in_sizes, int n_in,
                              void* d_out, int out_size) {
    const float* x     = (const float*)d_in[0];
    const int*   adj   = (const int*)d_in[1];
    const float* W_in  = (const float*)d_in[2];
    const float* a_in  = (const float*)d_in[3];
    const float* W_hid = (const float*)d_in[4];
    const float* a_hid = (const float*)d_in[5];
    const float* W_out = (const float*)d_in[6];
    const float* a_out = (const float*)d_in[7];
    float* out = (float*)d_out;

    // smem: 4*B slots + 2*W bufs + 4*E slots + Zs
    const int SMEM_L1 = 4 * (128 * 40 * 4) + 2 * (64 * 40 * 4)  + 4 * 384 + 512;   // ~105KB
    const int SMEM_L2 = 4 * (64 * 40 * 4)  + 2 * (128 * 40 * 4) + 4 * 384 + 768;   // ~84KB
    cudaFuncSetAttribute(aggW3_k<128, 64>, cudaFuncAttributeMaxDynamicSharedMemorySize, SMEM_L1);
    cudaFuncSetAttribute(aggW3_k<64, 128>, cudaFuncAttributeMaxDynamicSharedMemorySize, SMEM_L2);

    // Layer 1 (aggW3_k<128,64> is launch #4 -> ncu profiles it)
    gemm_k<64, 64, 4, 4, 0><<<dim3(64, 2, 4), 256>>>(x, W_in, 128, 128);          // 1
    scores_pack_k<<<2048 + 2048, 256>>>(a_in, 128, NHEADS * NNODES, adj, 2048);   // 2
    transpose_tf32_k<128><<<dim3(128, 4, 4), 256>>>();                            // 3
    aggW3_k<128, 64><<<dim3(64, 4), 256, SMEM_L1>>>(x);                           // 4

    // Layer 2
    gemm_k<64, 64, 4, 4, 1><<<dim3(64, 1, 4), 256>>>(nullptr, W_hid, 512, 64);
    scores_k<<<(NHEADS * NNODES) / 8, 256>>>(a_hid, 64, NHEADS * NNODES);
    transpose_tf32_k<64><<<dim3(128, 2, 4), 256>>>();
    aggW3_k<64, 128><<<dim3(32, 4), 256, SMEM_L2>>>(nullptr);

    // Layer 3
    gemm_k<64, 16, 4, 1, 2><<<dim3(64, 1, 1), 256>>>(nullptr, W_out, 256, 16);
    scores_k<<<NNODES / 8, 256>>>(a_out, 16, NNODES);
    agg3_k<<<dim3(128, 1, 1), 128>>>();

    logsoftmax_k<<<NNODES / 8, 256>>>(out);
}

// round 15
// speedup vs baseline: 1.6771x; 1.4340x over previous
#include <cuda_runtime.h>
#include <cuda_bf16.h>
#include <cstdint>
#include <math.h>

#define NNODES 4096
#define NW 128
#define NHEADS 4

typedef unsigned long long ull;

// ---------------- scratch ----------------
__device__ unsigned g_adjbits[NNODES * NW];
__device__ float g_hf[NHEADS * NNODES * 128];
__device__ float g_E1[NHEADS * NNODES];
__device__ float g_E1s[NHEADS * NNODES];
__device__ float2 g_E2p[NHEADS * NNODES];      // (E2, E2s) interleaved
__device__ float g_cat1[NNODES * 512];
__device__ float g_cat2[NNODES * 256];
__device__ float g_h3[NNODES * 16];
__device__ float g_hT[NHEADS * 128 * NNODES];  // [h][d][m'], tf32, m pair-permuted

__device__ __forceinline__ float eluf(float v) { return v > 0.f ? v : expm1f(v); }

__device__ __forceinline__ uint32_t smem_u32(const void* p) {
    uint32_t a;
    asm("{ .reg .u64 t; cvta.to.shared.u64 t, %1; cvt.u32.u64 %0, t; }" : "=r"(a) : "l"(p));
    return a;
}
__device__ __forceinline__ uint32_t tf32u(float v) {
    uint32_t r;
    asm("cvt.rna.tf32.f32 %0, %1;" : "=r"(r) : "f"(v));
    return r;
}
__device__ __forceinline__ ull dupf(float v) {
    ull r; asm("mov.b64 %0, {%1, %1};" : "=l"(r) : "f"(v)); return r;
}
__device__ __forceinline__ void ffma2(ull& acc, ull a, ull b) {
    asm("fma.rn.f32x2 %0, %1, %2, %0;" : "+l"(acc) : "l"(a), "l"(b));
}
__device__ __forceinline__ float2 unpack2(ull v) {
    float2 r; asm("mov.b64 {%0, %1}, %2;" : "=f"(r.x), "=f"(r.y) : "l"(v)); return r;
}

#define CP16(dst, src) \
    asm volatile("cp.async.cg.shared.global [%0], [%1], 16;" :: "r"(dst), "l"(src))
#define CP_COMMIT() asm volatile("cp.async.commit_group;" ::: "memory")
#define CP_WAIT(n)  asm volatile("cp.async.wait_group %0;" :: "n"(n) : "memory")

__device__ __forceinline__ void mma_tf32(float* c, uint32_t a0, uint32_t a1,
                                         uint32_t a2, uint32_t a3,
                                         uint32_t b0, uint32_t b1) {
    asm volatile(
        "mma.sync.aligned.m16n8k8.row.col.f32.tf32.tf32.f32 "
        "{%0,%1,%2,%3}, {%4,%5,%6,%7}, {%8,%9}, {%0,%1,%2,%3};"
        : "+f"(c[0]), "+f"(c[1]), "+f"(c[2]), "+f"(c[3])
        : "r"(a0), "r"(a1), "r"(a2), "r"(a3), "r"(b0), "r"(b1));
}

// ---------------- feature GEMM (f32x2 inner product) ----------------
template<int TN, int TD, int MR, int NC, int SRC>
__global__ __launch_bounds__(256) void gemm_k(const float* __restrict__ Aext,
                                              const float* __restrict__ W,
                                              int K, int Dtot) {
    const int TK = 16;
    __shared__ __align__(16) float As[TK][TN];
    __shared__ __align__(16) float Bs[TK][TD];
    const float* A = (SRC == 0) ? Aext : (SRC == 1 ? g_cat1 : g_cat2);

    int t = threadIdx.x;
    int n0 = blockIdx.x * TN;
    int d0 = blockIdx.y * TD;
    int h  = blockIdx.z;
    const float* Wh = W + (size_t)h * K * Dtot;
    const int rg = t / (TD / NC);
    const int cg = t % (TD / NC);

    constexpr int NC2 = (NC & 1) ? 0 : NC / 2;
    ull accp[MR][NC2 ? NC2 : 1];
    float accs[MR][NC2 ? 1 : NC];
#pragma unroll
    for (int i = 0; i < MR; i++) {
        if (NC2) {
#pragma unroll
            for (int j = 0; j < (NC2 ? NC2 : 1); j++) accp[i][j] = 0ull;
        } else {
#pragma unroll
            for (int j = 0; j < (NC2 ? 1 : NC); j++) accs[i][j] = 0.f;
        }
    }

    for (int k0 = 0; k0 < K; k0 += TK) {
        for (int idx = t; idx < TN * (TK / 4); idx += 256) {
            int i_n = idx / (TK / 4);
            int k4  = idx % (TK / 4);
            float4 v = *(const float4*)&A[(size_t)(n0 + i_n) * K + k0 + 4 * k4];
            As[4 * k4 + 0][i_n] = v.x;
            As[4 * k4 + 1][i_n] = v.y;
            As[4 * k4 + 2][i_n] = v.z;
            As[4 * k4 + 3][i_n] = v.w;
        }
        for (int idx = t; idx < TK * (TD / 4); idx += 256) {
            int kk = idx / (TD / 4);
            int j4 = idx % (TD / 4);
            *(float4*)&Bs[kk][4 * j4] =
                *(const float4*)&Wh[(size_t)(k0 + kk) * Dtot + d0 + 4 * j4];
        }
        __syncthreads();
#pragma unroll
        for (int k = 0; k < TK; k++) {
            if (NC2) {
                ull bp[NC2 ? NC2 : 1];
#pragma unroll
                for (int j = 0; j < (NC2 ? NC2 : 1); j++)
                    bp[j] = *(const ull*)&Bs[k][cg * NC + 2 * j];
#pragma unroll
                for (int i = 0; i < MR; i++) {
                    ull ad = dupf(As[k][rg * MR + i]);
#pragma unroll
                    for (int j = 0; j < (NC2 ? NC2 : 1); j++)
                        ffma2(accp[i][j], ad, bp[j]);
                }
            } else {
                float a_[MR], b_[NC];
#pragma unroll
                for (int i = 0; i < MR; i++) a_[i] = As[k][rg * MR + i];
#pragma unroll
                for (int j = 0; j < NC; j++) b_[j] = Bs[k][cg * NC + j];
#pragma unroll
                for (int i = 0; i < MR; i++)
#pragma unroll
                    for (int j = 0; j < NC; j++)
                        accs[i][j] = fmaf(a_[i], b_[j], accs[i][j]);
            }
        }
        __syncthreads();
    }
    float* Ch = g_hf + (size_t)h * NNODES * Dtot;
#pragma unroll
    for (int i = 0; i < MR; i++) {
        float* row = &Ch[(size_t)(n0 + rg * MR + i) * Dtot + d0 + cg * NC];
        if (NC2) {
#pragma unroll
            for (int j = 0; j < (NC2 ? NC2 : 1); j++) {
                float2 v = unpack2(accp[i][j]);
                row[2 * j]     = v.x;
                row[2 * j + 1] = v.y;
            }
        } else {
#pragma unroll
            for (int j = 0; j < (NC2 ? 1 : NC); j++) row[j] = accs[i][j];
        }
    }
}

// ---------------- scores (optionally fused with adjacency bit-pack) ----------------
__device__ __forceinline__ void scores_body(const float* a, int D, int total,
                                            int blk, int t) {
    int gid  = blk * 8 + (t >> 5);
    int lane = t & 31;
    if (gid >= total) return;
    int h = gid / NNODES, n = gid % NNODES;
    const float* hr = g_hf + ((size_t)h * NNODES + n) * D;
    const float* a1 = a + (size_t)h * 2 * D;
    const float* a2 = a1 + D;
    float s1 = 0.f, s2 = 0.f;
    for (int d = lane; d < D; d += 32) {
        float v = hr[d];
        s1 += v * a1[d];
        s2 += v * a2[d];
    }
#pragma unroll
    for (int o = 16; o; o >>= 1) {
        s1 += __shfl_xor_sync(~0u, s1, o);
        s2 += __shfl_xor_sync(~0u, s2, o);
    }
    if (!lane) {
        int idx = h * NNODES + n;
        g_E1[idx]  = expf(s1);
        g_E1s[idx] = expf(0.2f * s1);
        g_E2p[idx] = make_float2(expf(s2), expf(0.2f * s2));
    }
}

__global__ __launch_bounds__(256) void scores_k(const float* __restrict__ a, int D, int total) {
    scores_body(a, D, total, blockIdx.x, threadIdx.x);
}

__global__ __launch_bounds__(256) void scores_pack_k(const float* __restrict__ a, int D,
                                                     int total, const int* __restrict__ adj,
                                                     int scoreBlocks) {
    if ((int)blockIdx.x < scoreBlocks) {
        scores_body(a, D, total, blockIdx.x, threadIdx.x);
        return;
    }
    int wi = (blockIdx.x - scoreBlocks) * 256 + threadIdx.x;
    if (wi >= NNODES * NW) return;
    const int4* p = (const int4*)adj + (size_t)wi * 8;
    unsigned w = 0;
#pragma unroll
    for (int q = 0; q < 8; q++) {
        int4 v = p[q];
        if (v.x > 0) w |= 1u << (q * 4 + 0);
        if (v.y > 0) w |= 1u << (q * 4 + 1);
        if (v.z > 0) w |= 1u << (q * 4 + 2);
        if (v.w > 0) w |= 1u << (q * 4 + 3);
    }
    g_adjbits[wi] = w;
}

// ---------------- transpose + tf32 + m-pair-permute ----------------
// m' = (m & ~7) + 2*(m&3) + ((m>>2)&1)  so mma fragment pairs (m, m+4) are adjacent.
template<int D>
__global__ __launch_bounds__(256) void transpose_tf32_k() {
    __shared__ float ts[32][33];
    int t  = threadIdx.x;
    int nt = blockIdx.x, dt = blockIdx.y, h = blockIdx.z;
    int r0 = t / 32, c = t % 32;
#pragma unroll
    for (int p = 0; p < 4; p++) {
        int r = p * 8 + r0;
        ts[r][c] = g_hf[((size_t)h * NNODES + nt * 32 + r) * D + dt * 32 + c];
    }
    __syncthreads();
    const int cperm = (c & ~7) + 2 * (c & 3) + ((c >> 2) & 1);
#pragma unroll
    for (int p = 0; p < 4; p++) {
        int dr = p * 8 + r0;
        uint32_t v = tf32u(ts[c][dr]);
        size_t addr = ((size_t)h * D + dt * 32 + dr) * NNODES + nt * 32 + cperm;
        g_hT[addr] = __uint_as_float(v);
    }
}

// ---------------- tf32 mma aggregation v5: max-trick weights ----------------
// w(n,m) = adj(n,m) ? max(E1[n]*E2[m], E1s[n]*E2s[m]) : 0   (leakyrelu == max identity)
// CTA: ROWS n-rows x D cols, 256 threads (8 warps). Warp tile 32x32.
// Chunk=32 m. B/E: 4-slot cp.async ring. W: double buffer, computed 1 chunk ahead.
template<int D, int ROWS>
__global__ __launch_bounds__(256)
void aggW3_k(const float* __restrict__ resid) {
    constexpr int NCG  = D / 32;
    constexpr int NCH  = NNODES / 32;
    constexpr int BST  = 40;                   // floats per B/W row
    constexpr int BBUF = D * BST * 4;          // bytes per B slot
    constexpr int WBUF = ROWS * BST * 4;       // bytes per W buffer
    constexpr int O_W  = 4 * BBUF;
    constexpr int O_E  = O_W + 2 * WBUF;
    constexpr int ESL  = 256;                  // e2p[32] per slot
    constexpr int O_Z  = O_E + 4 * ESL;
    constexpr int R    = ROWS / 64;            // weight rows per thread

    extern __shared__ __align__(16) char sm[];
    const uint32_t sb = smem_u32(sm);
    float* Zs = (float*)(sm + O_Z);

    const int t = threadIdx.x, lane = t & 31, wid = t >> 5;
    const int cg = wid % NCG, rg = wid / NCG;
    const int n0 = blockIdx.x * ROWS;
    const int head = blockIdx.y;
    const int headN = head * NNODES;
    const int rq  = lane >> 2;
    const int k0b = lane & 3;
    const int i4  = t & 3;
    const int wr0 = t >> 2;                    // weight row (0..63), +64 if R=2

    float E1r[R], E1sr[R];
    const unsigned* adjp[R];
#pragma unroll
    for (int r = 0; r < R; r++) {
        int row = wr0 + r * 64;
        E1r[r]  = g_E1[headN + n0 + row];
        E1sr[r] = g_E1s[headN + n0 + row];
        adjp[r] = g_adjbits + (size_t)(n0 + row) * NW;
    }
    float zacc[R];
#pragma unroll
    for (int r = 0; r < R; r++) zacc[r] = 0.f;

    float acc[2][4][4];
#pragma unroll
    for (int mg = 0; mg < 2; mg++)
#pragma unroll
        for (int ng = 0; ng < 4; ng++)
#pragma unroll
            for (int q = 0; q < 4; q++) acc[mg][ng][q] = 0.f;

    auto fill = [&](int chunk) {
        const int slot = chunk & 3;
        for (int idx = t; idx < D * 8; idx += 256) {
            int row = idx >> 3, c8 = idx & 7;
            uint32_t dst = sb + (uint32_t)(slot * BBUF + (row * BST + c8 * 4) * 4);
            size_t s = ((size_t)(head * D + row)) * NNODES + chunk * 32 + c8 * 4;
            CP16(dst, (const void*)(g_hT + s));
        }
        if (t < 16) {           // e2 pairs: 32 float2 = 256B
            uint32_t dst = sb + (uint32_t)(O_E + slot * ESL + t * 16);
            CP16(dst, (const void*)(g_E2p + headN + chunk * 32 + t * 2));
        }
    };

    auto weights = [&](int chunk) {
        const int slot = chunk & 3;
        const float2* e2p = (const float2*)(sm + O_E + slot * ESL);
        float* Wb = (float*)(sm + O_W + (chunk & 1) * WBUF);
#pragma unroll
        for (int r = 0; r < R; r++) {
            unsigned mw = adjp[r][chunk];
            float* wrow = Wb + (wr0 + r * 64) * BST;
            float zl = 0.f;
#pragma unroll
            for (int blk = 0; blk < 4; blk++) {
                float w2[2];
#pragma unroll
                for (int half = 0; half < 2; half++) {
                    int m = blk * 8 + half * 4 + i4;
                    float2 ep = e2p[m];
                    float w = fmaxf(E1r[r] * ep.x, E1sr[r] * ep.y);
                    w = ((mw >> m) & 1u) ? w : 0.f;
                    zl += w;
                    w2[half] = __uint_as_float(tf32u(w));
                }
                *(float2*)&wrow[blk * 8 + 2 * i4] = make_float2(w2[0], w2[1]);
            }
            zacc[r] += zl;
        }
    };

    auto mmastep = [&](int chunk) {
        const float* Bs = (const float*)(sm + (chunk & 3) * BBUF);
        const float* Wb = (const float*)(sm + O_W + (chunk & 1) * WBUF);
#pragma unroll
        for (int ks = 0; ks < 4; ks++) {
            const int cw = ks * 8 + 2 * k0b;
            uint2 a0[2], a1[2];
#pragma unroll
            for (int mg = 0; mg < 2; mg++) {
                const float* w0 = Wb + (rg * 32 + mg * 16 + rq) * BST + cw;
                a0[mg] = *(const uint2*)w0;
                a1[mg] = *(const uint2*)(w0 + 8 * BST);
            }
#pragma unroll
            for (int ng = 0; ng < 4; ng++) {
                const float* bp = Bs + (cg * 32 + ng * 8 + rq) * BST + cw;
                uint2 b = *(const uint2*)bp;
#pragma unroll
                for (int mg = 0; mg < 2; mg++)
                    mma_tf32(acc[mg][ng], a0[mg].x, a1[mg].x, a0[mg].y, a1[mg].y,
                             b.x, b.y);
            }
        }
    };

    // prologue
    fill(0); CP_COMMIT();
    fill(1); CP_COMMIT();
    CP_WAIT(1);
    __syncthreads();
    weights(0);

    for (int c = 0; c < NCH; c++) {
        if (c + 2 < NCH) { fill(c + 2); CP_COMMIT(); CP_WAIT(1); }
        else             { CP_WAIT(0); }
        __syncthreads();            // W(c), B(c), E(c+1) visible; chunk c-1 readers done
        if (c + 1 < NCH) weights(c + 1);
        mmastep(c);
    }

    // Z reduce over quad (4 threads per row)
#pragma unroll
    for (int r = 0; r < R; r++) {
        float z = zacc[r];
        z += __shfl_xor_sync(~0u, z, 1);
        z += __shfl_xor_sync(~0u, z, 2);
        if (i4 == 0) Zs[wr0 + r * 64] = 1.f / z;
    }
    __syncthreads();

    float* out = (D == 128) ? g_cat1 : g_cat2;
    const int ostr = (D == 128) ? 512 : 256;
#pragma unroll
    for (int mg = 0; mg < 2; mg++) {
        int lr = rg * 32 + mg * 16 + rq;
        float zi0 = Zs[lr], zi1 = Zs[lr + 8];
        int n = n0 + lr;
#pragma unroll
        for (int ng = 0; ng < 4; ng++) {
            int col = cg * 32 + ng * 8 + (lane & 3) * 2;
            float v0 = acc[mg][ng][0] * zi0, v1 = acc[mg][ng][1] * zi0;
            float v2 = acc[mg][ng][2] * zi1, v3 = acc[mg][ng][3] * zi1;
            if (D == 128) {
                float2 ra = *(const float2*)&resid[(size_t)n * 128 + col];
                float2 rb = *(const float2*)&resid[(size_t)(n + 8) * 128 + col];
                v0 += ra.x; v1 += ra.y; v2 += rb.x; v3 += rb.y;
            }
            float2 o0 = {eluf(v0), eluf(v1)};
            float2 o1 = {eluf(v2), eluf(v3)};
            *(float2*)&out[(size_t)n * ostr + head * D + col]       = o0;
            *(float2*)&out[(size_t)(n + 8) * ostr + head * D + col] = o1;
        }
    }
}

// ---------------- SIMT agg for layer 3 (D=16), max-trick ----------------
__global__ __launch_bounds__(128) void agg3_k() {
    const int D = 16, TN = 32, TM = 32, MR = 2, NC = 2;
    __shared__ __align__(16) float hs[2][TM][D];
    __shared__ __align__(16) float ws[2][TM][TN + 2];
    __shared__ float Zred[128];
    __shared__ float Zs[TN];

    const int t  = threadIdx.x;
    const int n0 = blockIdx.x * TN;
    const float* hfh = g_hf;

    const int rA = t % TN;
    const int G  = 128 / TN;
    const int g  = t / TN;
    const int MMPT = TM / G;

    const float rE1  = g_E1[n0 + rA];
    const float rE1s = g_E1s[n0 + rA];
    float zacc = 0.f;

    const int rg = t / (D / NC);
    const int cg = t % (D / NC);

    ull acc[NC];
#pragma unroll
    for (int j = 0; j < NC; j++) acc[j] = 0ull;

    auto fill = [&](int wti, int buf) {
        int m0 = wti * TM;
        for (int idx = t; idx < TM * (D / 4); idx += 128) {
            int m  = idx / (D / 4);
            int dd = idx % (D / 4);
            *(float4*)&hs[buf][m][4 * dd] = *(const float4*)&hfh[(size_t)(m0 + m) * D + 4 * dd];
        }
        unsigned aw = g_adjbits[(size_t)(n0 + rA) * NW + wti];
#pragma unroll
        for (int j = 0; j < MMPT; j++) {
            int mm = g + G * j;
            float w = 0.f;
            if ((aw >> mm) & 1u) {
                float2 ep = g_E2p[m0 + mm];
                w = fmaxf(rE1 * ep.x, rE1s * ep.y);
            }
            ws[buf][mm][rA] = w;
            zacc += w;
        }
    };

    fill(0, 0);
    __syncthreads();
    const int NT = NNODES / TM;
    for (int mt = 0; mt < NT; mt++) {
        int cur = mt & 1;
        if (mt + 1 < NT) fill(mt + 1, cur ^ 1);
#pragma unroll
        for (int k = 0; k < TM; k++) {
            ull a2 = *(const ull*)&ws[cur][k][rg * MR];
#pragma unroll
            for (int j = 0; j < NC; j++) {
                ull bb = dupf(hs[cur][k][cg * NC + j]);
                ffma2(acc[j], a2, bb);
            }
        }
        __syncthreads();
    }
    Zred[t] = zacc;
    __syncthreads();
    if (t < TN) {
        float z = 0.f;
#pragma unroll
        for (int q = 0; q < G; q++) z += Zred[t + q * TN];
        Zs[t] = 1.f / z;
    }
    __syncthreads();
    {
        int lr0 = rg * MR;
        float zi0 = Zs[lr0], zi1 = Zs[lr0 + 1];
#pragma unroll
        for (int j = 0; j < NC; j++) {
            float2 v = unpack2(acc[j]);
            int d = cg * NC + j;
            g_h3[(size_t)(n0 + lr0) * 16 + d]     = eluf(v.x * zi0);
            g_h3[(size_t)(n0 + lr0 + 1) * 16 + d] = eluf(v.y * zi1);
        }
    }
}

// ---------------- final log-softmax ----------------
__global__ __launch_bounds__(256) void logsoftmax_k(float* __restrict__ out) {
    int n    = blockIdx.x * 8 + (threadIdx.x >> 5);
    int lane = threadIdx.x & 31;
    if (n >= NNODES) return;
    float v = (lane < 16) ? g_h3[n * 16 + lane] : -INFINITY;
    float m = v;
#pragma unroll
    for (int o = 16; o; o >>= 1) m = fmaxf(m, __shfl_xor_sync(~0u, m, o));
    float e = (lane < 16) ? expf(v - m) : 0.f;
    float s = e;
#pragma unroll
    for (int o = 16; o; o >>= 1) s += __shfl_xor_sync(~0u, s, o);
    if (lane < 16) out[n * 16 + lane] = v - m - logf(s);
}

// ---------------- launch ----------------
extern "C" void kernel_launch(void* const* d_in, const int* in_sizes, int n_in,
                              void* d_out, int out_size) {
    const float* x     = (const float*)d_in[0];
    const int*   adj   = (const int*)d_in[1];
    const float* W_in  = (const float*)d_in[2];
    const float* a_in  = (const float*)d_in[3];
    const float* W_hid = (const float*)d_in[4];
    const float* a_hid = (const float*)d_in[5];
    const float* W_out = (const float*)d_in[6];
    const float* a_out = (const float*)d_in[7];
    float* out = (float*)d_out;

    // smem: 4*B slots + 2*W bufs + 4*E slots + Zs
    const int SMEM_L1 = 4 * (128 * 40 * 4) + 2 * (64 * 40 * 4)  + 4 * 256 + 512;   // ~104KB
    const int SMEM_L2 = 4 * (64 * 40 * 4)  + 2 * (128 * 40 * 4) + 4 * 256 + 768;   // ~84KB
    cudaFuncSetAttribute(aggW3_k<128, 64>, cudaFuncAttributeMaxDynamicSharedMemorySize, SMEM_L1);
    cudaFuncSetAttribute(aggW3_k<64, 128>, cudaFuncAttributeMaxDynamicSharedMemorySize, SMEM_L2);

    // Layer 1 (aggW3_k<128,64> is launch #4 -> ncu profiles it)
    gemm_k<64, 64, 4, 4, 0><<<dim3(64, 2, 4), 256>>>(x, W_in, 128, 128);          // 1
    scores_pack_k<<<2048 + 2048, 256>>>(a_in, 128, NHEADS * NNODES, adj, 2048);   // 2
    transpose_tf32_k<128><<<dim3(128, 4, 4), 256>>>();                            // 3
    aggW3_k<128, 64><<<dim3(64, 4), 256, SMEM_L1>>>(x);                           // 4

    // Layer 2
    gemm_k<64, 64, 4, 4, 1><<<dim3(64, 1, 4), 256>>>(nullptr, W_hid, 512, 64);
    scores_k<<<(NHEADS * NNODES) / 8, 256>>>(a_hid, 64, NHEADS * NNODES);
    transpose_tf32_k<64><<<dim3(128, 2, 4), 256>>>();
    aggW3_k<64, 128><<<dim3(32, 4), 256, SMEM_L2>>>(nullptr);

    // Layer 3
    gemm_k<64, 16, 4, 1, 2><<<dim3(64, 1, 1), 256>>>(nullptr, W_out, 256, 16);
    scores_k<<<NNODES / 8, 256>>>(a_out, 16, NNODES);
    agg3_k<<<dim3(128, 1, 1), 128>>>();

    logsoftmax_k<<<NNODES / 8, 256>>>(out);
}

// round 16
// speedup vs baseline: 1.7746x; 1.0582x over previous
#include <cuda_runtime.h>
#include <cuda_bf16.h>
#include <cstdint>
#include <math.h>

#define NNODES 4096
#define NW 128
#define NHEADS 4

typedef unsigned long long ull;

// ---------------- scratch ----------------
__device__ unsigned g_adjbits[NNODES * NW];
__device__ float g_hf[NHEADS * NNODES * 128];
__device__ float g_E1[NHEADS * NNODES];
__device__ float g_E1s[NHEADS * NNODES];
__device__ float g_E2a[NHEADS * NNODES];       // E2, pair-permuted within 32-blocks
__device__ float g_E2sa[NHEADS * NNODES];      // E2s, pair-permuted
__device__ float2 g_E2p[NHEADS * NNODES];      // (E2, E2s) natural order (agg3)
__device__ float g_cat1[NNODES * 512];
__device__ float g_cat2[NNODES * 256];
__device__ float g_h3[NNODES * 16];
__device__ float g_hT[NHEADS * 128 * NNODES];  // [h][d][m'], tf32, m pair-permuted
__device__ float g_part[2 * NHEADS * NNODES * 128];   // m-split partials (16MB)
__device__ float g_pz[2 * NHEADS * NNODES];           // m-split Z partials

__device__ __forceinline__ float eluf(float v) { return v > 0.f ? v : expm1f(v); }

__device__ __forceinline__ uint32_t smem_u32(const void* p) {
    uint32_t a;
    asm("{ .reg .u64 t; cvta.to.shared.u64 t, %1; cvt.u32.u64 %0, t; }" : "=r"(a) : "l"(p));
    return a;
}
__device__ __forceinline__ uint32_t tf32u(float v) {
    uint32_t r;
    asm("cvt.rna.tf32.f32 %0, %1;" : "=r"(r) : "f"(v));
    return r;
}
__device__ __forceinline__ ull dupf(float v) {
    ull r; asm("mov.b64 %0, {%1, %1};" : "=l"(r) : "f"(v)); return r;
}
__device__ __forceinline__ void ffma2(ull& acc, ull a, ull b) {
    asm("fma.rn.f32x2 %0, %1, %2, %0;" : "+l"(acc) : "l"(a), "l"(b));
}
__device__ __forceinline__ ull mul2(ull a, ull b) {
    ull r; asm("mul.rn.f32x2 %0, %1, %2;" : "=l"(r) : "l"(a), "l"(b)); return r;
}
__device__ __forceinline__ float2 unpack2(ull v) {
    float2 r; asm("mov.b64 {%0, %1}, %2;" : "=f"(r.x), "=f"(r.y) : "l"(v)); return r;
}

#define CP16(dst, src) \
    asm volatile("cp.async.cg.shared.global [%0], [%1], 16;" :: "r"(dst), "l"(src))
#define CP_COMMIT() asm volatile("cp.async.commit_group;" ::: "memory")
#define CP_WAIT(n)  asm volatile("cp.async.wait_group %0;" :: "n"(n) : "memory")

__device__ __forceinline__ void mma_tf32(float* c, uint32_t a0, uint32_t a1,
                                         uint32_t a2, uint32_t a3,
                                         uint32_t b0, uint32_t b1) {
    asm volatile(
        "mma.sync.aligned.m16n8k8.row.col.f32.tf32.tf32.f32 "
        "{%0,%1,%2,%3}, {%4,%5,%6,%7}, {%8,%9}, {%0,%1,%2,%3};"
        : "+f"(c[0]), "+f"(c[1]), "+f"(c[2]), "+f"(c[3])
        : "r"(a0), "r"(a1), "r"(a2), "r"(a3), "r"(b0), "r"(b1));
}

// ---------------- feature GEMM (f32x2 inner product) ----------------
template<int TN, int TD, int MR, int NC, int SRC>
__global__ __launch_bounds__(256) void gemm_k(const float* __restrict__ Aext,
                                              const float* __restrict__ W,
                                              int K, int Dtot) {
    const int TK = 16;
    __shared__ __align__(16) float As[TK][TN];
    __shared__ __align__(16) float Bs[TK][TD];
    const float* A = (SRC == 0) ? Aext : (SRC == 1 ? g_cat1 : g_cat2);

    int t = threadIdx.x;
    int n0 = blockIdx.x * TN;
    int d0 = blockIdx.y * TD;
    int h  = blockIdx.z;
    const float* Wh = W + (size_t)h * K * Dtot;
    const int rg = t / (TD / NC);
    const int cg = t % (TD / NC);

    constexpr int NC2 = (NC & 1) ? 0 : NC / 2;
    ull accp[MR][NC2 ? NC2 : 1];
    float accs[MR][NC2 ? 1 : NC];
#pragma unroll
    for (int i = 0; i < MR; i++) {
        if (NC2) {
#pragma unroll
            for (int j = 0; j < (NC2 ? NC2 : 1); j++) accp[i][j] = 0ull;
        } else {
#pragma unroll
            for (int j = 0; j < (NC2 ? 1 : NC); j++) accs[i][j] = 0.f;
        }
    }

    for (int k0 = 0; k0 < K; k0 += TK) {
        for (int idx = t; idx < TN * (TK / 4); idx += 256) {
            int i_n = idx / (TK / 4);
            int k4  = idx % (TK / 4);
            float4 v = *(const float4*)&A[(size_t)(n0 + i_n) * K + k0 + 4 * k4];
            As[4 * k4 + 0][i_n] = v.x;
            As[4 * k4 + 1][i_n] = v.y;
            As[4 * k4 + 2][i_n] = v.z;
            As[4 * k4 + 3][i_n] = v.w;
        }
        for (int idx = t; idx < TK * (TD / 4); idx += 256) {
            int kk = idx / (TD / 4);
            int j4 = idx % (TD / 4);
            *(float4*)&Bs[kk][4 * j4] =
                *(const float4*)&Wh[(size_t)(k0 + kk) * Dtot + d0 + 4 * j4];
        }
        __syncthreads();
#pragma unroll
        for (int k = 0; k < TK; k++) {
            if (NC2) {
                ull bp[NC2 ? NC2 : 1];
#pragma unroll
                for (int j = 0; j < (NC2 ? NC2 : 1); j++)
                    bp[j] = *(const ull*)&Bs[k][cg * NC + 2 * j];
#pragma unroll
                for (int i = 0; i < MR; i++) {
                    ull ad = dupf(As[k][rg * MR + i]);
#pragma unroll
                    for (int j = 0; j < (NC2 ? NC2 : 1); j++)
                        ffma2(accp[i][j], ad, bp[j]);
                }
            } else {
                float a_[MR], b_[NC];
#pragma unroll
                for (int i = 0; i < MR; i++) a_[i] = As[k][rg * MR + i];
#pragma unroll
                for (int j = 0; j < NC; j++) b_[j] = Bs[k][cg * NC + j];
#pragma unroll
                for (int i = 0; i < MR; i++)
#pragma unroll
                    for (int j = 0; j < NC; j++)
                        accs[i][j] = fmaf(a_[i], b_[j], accs[i][j]);
            }
        }
        __syncthreads();
    }
    float* Ch = g_hf + (size_t)h * NNODES * Dtot;
#pragma unroll
    for (int i = 0; i < MR; i++) {
        float* row = &Ch[(size_t)(n0 + rg * MR + i) * Dtot + d0 + cg * NC];
        if (NC2) {
#pragma unroll
            for (int j = 0; j < (NC2 ? NC2 : 1); j++) {
                float2 v = unpack2(accp[i][j]);
                row[2 * j]     = v.x;
                row[2 * j + 1] = v.y;
            }
        } else {
#pragma unroll
            for (int j = 0; j < (NC2 ? 1 : NC); j++) row[j] = accs[i][j];
        }
    }
}

// ---------------- scores ----------------
__device__ __forceinline__ void scores_body(const float* a, int D, int total,
                                            int blk, int t) {
    int gid  = blk * 8 + (t >> 5);
    int lane = t & 31;
    if (gid >= total) return;
    int h = gid / NNODES, n = gid % NNODES;
    const float* hr = g_hf + ((size_t)h * NNODES + n) * D;
    const float* a1 = a + (size_t)h * 2 * D;
    const float* a2 = a1 + D;
    float s1 = 0.f, s2 = 0.f;
    for (int d = lane; d < D; d += 32) {
        float v = hr[d];
        s1 += v * a1[d];
        s2 += v * a2[d];
    }
#pragma unroll
    for (int o = 16; o; o >>= 1) {
        s1 += __shfl_xor_sync(~0u, s1, o);
        s2 += __shfl_xor_sync(~0u, s2, o);
    }
    if (!lane) {
        int idx = h * NNODES + n;
        float e2  = expf(s2);
        float e2s = expf(0.2f * s2);
        g_E1[idx]  = expf(s1);
        g_E1s[idx] = expf(0.2f * s1);
        g_E2p[idx] = make_float2(e2, e2s);
        // pair-permuted copies (match mma fragment pair order)
        int j  = n & 31;
        int jp = (j & 24) | (2 * (j & 3) + ((j >> 2) & 1));
        int idxp = (idx & ~31) | jp;
        g_E2a[idxp]  = e2;
        g_E2sa[idxp] = e2s;
    }
}

__global__ __launch_bounds__(256) void scores_k(const float* __restrict__ a, int D, int total) {
    scores_body(a, D, total, blockIdx.x, threadIdx.x);
}

__global__ __launch_bounds__(256) void scores_pack_k(const float* __restrict__ a, int D,
                                                     int total, const int* __restrict__ adj,
                                                     int scoreBlocks) {
    if ((int)blockIdx.x < scoreBlocks) {
        scores_body(a, D, total, blockIdx.x, threadIdx.x);
        return;
    }
    int wi = (blockIdx.x - scoreBlocks) * 256 + threadIdx.x;
    if (wi >= NNODES * NW) return;
    const int4* p = (const int4*)adj + (size_t)wi * 8;
    unsigned w = 0;
#pragma unroll
    for (int q = 0; q < 8; q++) {
        int4 v = p[q];
        if (v.x > 0) w |= 1u << (q * 4 + 0);
        if (v.y > 0) w |= 1u << (q * 4 + 1);
        if (v.z > 0) w |= 1u << (q * 4 + 2);
        if (v.w > 0) w |= 1u << (q * 4 + 3);
    }
    g_adjbits[wi] = w;
}

// ---------------- transpose + tf32 + m-pair-permute ----------------
template<int D>
__global__ __launch_bounds__(256) void transpose_tf32_k() {
    __shared__ float ts[32][33];
    int t  = threadIdx.x;
    int nt = blockIdx.x, dt = blockIdx.y, h = blockIdx.z;
    int r0 = t / 32, c = t % 32;
#pragma unroll
    for (int p = 0; p < 4; p++) {
        int r = p * 8 + r0;
        ts[r][c] = g_hf[((size_t)h * NNODES + nt * 32 + r) * D + dt * 32 + c];
    }
    __syncthreads();
    const int cperm = (c & ~7) + 2 * (c & 3) + ((c >> 2) & 1);
#pragma unroll
    for (int p = 0; p < 4; p++) {
        int dr = p * 8 + r0;
        uint32_t v = tf32u(ts[c][dr]);
        size_t addr = ((size_t)h * D + dt * 32 + dr) * NNODES + nt * 32 + cperm;
        g_hT[addr] = __uint_as_float(v);
    }
}

// ---------------- tf32 mma aggregation v6: m-split, 2 B-slots, slim weights ----
// grid (ntiles, head, z) ; z = m-half. Partials (unnormalized acc + Z) to gmem.
template<int D, int ROWS>
__global__ __launch_bounds__(256) void aggW4_k() {
    constexpr int NCG  = D / 32;
    constexpr int NCH  = (NNODES / 32) / 2;    // 64 chunks per split
    constexpr int BST  = 40;
    constexpr int BBUF = D * BST * 4;
    constexpr int WBUF = ROWS * BST * 4;
    constexpr int O_W  = 2 * BBUF;
    constexpr int O_E  = O_W + 2 * WBUF;
    constexpr int ESL  = 256;                  // e2a[32] + e2sa[32]
    constexpr int R    = ROWS / 64;

    extern __shared__ __align__(16) char sm[];
    const uint32_t sb = smem_u32(sm);

    const int t = threadIdx.x, lane = t & 31, wid = t >> 5;
    const int cg = wid % NCG, rg = wid / NCG;
    const int n0 = blockIdx.x * ROWS;
    const int head = blockIdx.y;
    const int zz = blockIdx.z;
    const int cbase = zz * NCH;
    const int headN = head * NNODES;
    const int rq  = lane >> 2;
    const int k0b = lane & 3;
    const int i4  = t & 3;
    const int wr0 = t >> 2;

    ull e1d[R], e1sd[R];
    const unsigned* adjp[R];
#pragma unroll
    for (int r = 0; r < R; r++) {
        int row = wr0 + r * 64;
        e1d[r]  = dupf(g_E1[headN + n0 + row]);
        e1sd[r] = dupf(g_E1s[headN + n0 + row]);
        adjp[r] = g_adjbits + (size_t)(n0 + row) * NW + cbase;
    }
    float zacc[R];
#pragma unroll
    for (int r = 0; r < R; r++) zacc[r] = 0.f;

    float acc[2][4][4];
#pragma unroll
    for (int mg = 0; mg < 2; mg++)
#pragma unroll
        for (int ng = 0; ng < 4; ng++)
#pragma unroll
            for (int q = 0; q < 4; q++) acc[mg][ng][q] = 0.f;

    auto fillB = [&](int ch) {
        for (int idx = t; idx < D * 8; idx += 256) {
            int row = idx >> 3, c8 = idx & 7;
            uint32_t dst = sb + (uint32_t)((ch & 1) * BBUF + (row * BST + c8 * 4) * 4);
            size_t s = ((size_t)(head * D + row)) * NNODES + (cbase + ch) * 32 + c8 * 4;
            CP16(dst, (const void*)(g_hT + s));
        }
    };
    auto fillE = [&](int ch) {
        if (t < 8) {
            uint32_t dst = sb + (uint32_t)(O_E + (ch & 3) * ESL + t * 16);
            CP16(dst, (const void*)(g_E2a + headN + (cbase + ch) * 32 + t * 4));
        } else if (t < 16) {
            uint32_t dst = sb + (uint32_t)(O_E + (ch & 3) * ESL + 128 + (t - 8) * 16);
            CP16(dst, (const void*)(g_E2sa + headN + (cbase + ch) * 32 + (t - 8) * 4));
        }
    };
    auto weights = [&](int ch, const unsigned* mwv) {
        const float* e2a  = (const float*)(sm + O_E + (ch & 3) * ESL);
        const float* e2sa = e2a + 32;
        float* Wb = (float*)(sm + O_W + (ch & 1) * WBUF);
#pragma unroll
        for (int r = 0; r < R; r++) {
            unsigned msh = mwv[r] >> i4;
            float* wrow = Wb + (wr0 + r * 64) * BST;
            float zl = 0.f;
#pragma unroll
            for (int blk = 0; blk < 4; blk++) {
                ull q1 = *(const ull*)&e2a[blk * 8 + 2 * i4];
                ull q2 = *(const ull*)&e2sa[blk * 8 + 2 * i4];
                float2 A  = unpack2(mul2(e1d[r], q1));
                float2 Bv = unpack2(mul2(e1sd[r], q2));
                float w0 = fmaxf(A.x, Bv.x);
                float w1 = fmaxf(A.y, Bv.y);
                w0 = (msh & (1u << (blk * 8)))     ? w0 : 0.f;
                w1 = (msh & (1u << (blk * 8 + 4))) ? w1 : 0.f;
                zl += w0 + w1;
                *(float2*)&wrow[blk * 8 + 2 * i4] =
                    make_float2(__uint_as_float(tf32u(w0)), __uint_as_float(tf32u(w1)));
            }
            zacc[r] += zl;
        }
    };
    auto mmastep = [&](int ch) {
        const float* Bs = (const float*)(sm + (ch & 1) * BBUF);
        const float* Wb = (const float*)(sm + O_W + (ch & 1) * WBUF);
#pragma unroll
        for (int ks = 0; ks < 4; ks++) {
            const int cw = ks * 8 + 2 * k0b;
            uint2 a0[2], a1[2];
#pragma unroll
            for (int mg = 0; mg < 2; mg++) {
                const float* w0 = Wb + (rg * 32 + mg * 16 + rq) * BST + cw;
                a0[mg] = *(const uint2*)w0;
                a1[mg] = *(const uint2*)(w0 + 8 * BST);
            }
#pragma unroll
            for (int ng = 0; ng < 4; ng++) {
                const float* bp = Bs + (cg * 32 + ng * 8 + rq) * BST + cw;
                uint2 b = *(const uint2*)bp;
#pragma unroll
                for (int mg = 0; mg < 2; mg++)
                    mma_tf32(acc[mg][ng], a0[mg].x, a1[mg].x, a0[mg].y, a1[mg].y,
                             b.x, b.y);
            }
        }
    };

    // mask prefetch registers
    unsigned mw0[R], mwc[R], mwn[R];
#pragma unroll
    for (int r = 0; r < R; r++) {
        mw0[r] = adjp[r][0];
        mwc[r] = adjp[r][1];
        mwn[r] = adjp[r][2];
    }

    // prologue
    fillB(0); fillE(0); fillE(1); CP_COMMIT();
    CP_WAIT(0); __syncthreads();
    weights(0, mw0);

    for (int c = 0; c < NCH; c++) {
        __syncthreads();        // mma(c-1)/weights(c) complete CTA-wide
        if (c + 1 < NCH) {
            fillB(c + 1);
            if (c + 2 < NCH) fillE(c + 2);
            CP_COMMIT(); CP_WAIT(1);
            weights(c + 1, mwc);
#pragma unroll
            for (int r = 0; r < R; r++) mwc[r] = mwn[r];
            if (c + 3 < NCH) {
#pragma unroll
                for (int r = 0; r < R; r++) mwn[r] = adjp[r][c + 3];
            }
        } else {
            CP_WAIT(0);
        }
        mmastep(c);
    }

    // partial Z: quad reduce, write to gmem
#pragma unroll
    for (int r = 0; r < R; r++) {
        float z = zacc[r];
        z += __shfl_xor_sync(~0u, z, 1);
        z += __shfl_xor_sync(~0u, z, 2);
        if (i4 == 0)
            g_pz[(size_t)(zz * NHEADS + head) * NNODES + n0 + wr0 + r * 64] = z;
    }

    // partial numerator: raw acc to gmem
    float* P = g_part + ((size_t)(zz * NHEADS + head) * NNODES) * D;
#pragma unroll
    for (int mg = 0; mg < 2; mg++) {
        int lr = rg * 32 + mg * 16 + rq;
        int n = n0 + lr;
#pragma unroll
        for (int ng = 0; ng < 4; ng++) {
            int col = cg * 32 + ng * 8 + (lane & 3) * 2;
            *(float2*)&P[(size_t)n * D + col]       = make_float2(acc[mg][ng][0], acc[mg][ng][1]);
            *(float2*)&P[(size_t)(n + 8) * D + col] = make_float2(acc[mg][ng][2], acc[mg][ng][3]);
        }
    }
}

// ---------------- combine kernels ----------------
__global__ __launch_bounds__(256) void combine1_k(const float* __restrict__ x) {
    int e = blockIdx.x * 256 + threadIdx.x;       // float2 over 4*4096*64
    int h = e >> 18;
    int r = e & 0x3FFFF;
    int n = r >> 6;
    int d2 = r & 63;
    const float2* P = (const float2*)g_part;
    size_t i0 = ((size_t)h * NNODES + n) * 64 + d2;
    size_t i1 = i0 + (size_t)NHEADS * NNODES * 64;
    float2 a = P[i0], b = P[i1];
    float zi = 1.f / (g_pz[(size_t)h * NNODES + n] +
                      g_pz[(size_t)(NHEADS + h) * NNODES + n]);
    float2 rx = *(const float2*)&x[(size_t)n * 128 + 2 * d2];
    float2 o;
    o.x = eluf((a.x + b.x) * zi + rx.x);
    o.y = eluf((a.y + b.y) * zi + rx.y);
    *(float2*)&g_cat1[(size_t)n * 512 + h * 128 + 2 * d2] = o;
}

__global__ __launch_bounds__(256) void combine2_k() {
    int e = blockIdx.x * 256 + threadIdx.x;       // float2 over 4*4096*32
    int h = e >> 17;
    int r = e & 0x1FFFF;
    int n = r >> 5;
    int d2 = r & 31;
    const float2* P = (const float2*)g_part;
    size_t i0 = ((size_t)h * NNODES + n) * 32 + d2;
    size_t i1 = i0 + (size_t)NHEADS * NNODES * 32;
    float2 a = P[i0], b = P[i1];
    float zi = 1.f / (g_pz[(size_t)h * NNODES + n] +
                      g_pz[(size_t)(NHEADS + h) * NNODES + n]);
    float2 o;
    o.x = eluf((a.x + b.x) * zi);
    o.y = eluf((a.y + b.y) * zi);
    *(float2*)&g_cat2[(size_t)n * 256 + h * 64 + 2 * d2] = o;
}

// ---------------- SIMT agg for layer 3 (D=16), max-trick ----------------
__global__ __launch_bounds__(128) void agg3_k() {
    const int D = 16, TN = 32, TM = 32, MR = 2, NC = 2;
    __shared__ __align__(16) float hs[2][TM][D];
    __shared__ __align__(16) float ws[2][TM][TN + 2];
    __shared__ float Zred[128];
    __shared__ float Zs[TN];

    const int t  = threadIdx.x;
    const int n0 = blockIdx.x * TN;
    const float* hfh = g_hf;

    const int rA = t % TN;
    const int G  = 128 / TN;
    const int g  = t / TN;
    const int MMPT = TM / G;

    const float rE1  = g_E1[n0 + rA];
    const float rE1s = g_E1s[n0 + rA];
    float zacc = 0.f;

    const int rg = t / (D / NC);
    const int cg = t % (D / NC);

    ull acc[NC];
#pragma unroll
    for (int j = 0; j < NC; j++) acc[j] = 0ull;

    auto fill = [&](int wti, int buf) {
        int m0 = wti * TM;
        for (int idx = t; idx < TM * (D / 4); idx += 128) {
            int m  = idx / (D / 4);
            int dd = idx % (D / 4);
            *(float4*)&hs[buf][m][4 * dd] = *(const float4*)&hfh[(size_t)(m0 + m) * D + 4 * dd];
        }
        unsigned aw = g_adjbits[(size_t)(n0 + rA) * NW + wti];
#pragma unroll
        for (int j = 0; j < MMPT; j++) {
            int mm = g + G * j;
            float w = 0.f;
            if ((aw >> mm) & 1u) {
                float2 ep = g_E2p[m0 + mm];
                w = fmaxf(rE1 * ep.x, rE1s * ep.y);
            }
            ws[buf][mm][rA] = w;
            zacc += w;
        }
    };

    fill(0, 0);
    __syncthreads();
    const int NT = NNODES / TM;
    for (int mt = 0; mt < NT; mt++) {
        int cur = mt & 1;
        if (mt + 1 < NT) fill(mt + 1, cur ^ 1);
#pragma unroll
        for (int k = 0; k < TM; k++) {
            ull a2 = *(const ull*)&ws[cur][k][rg * MR];
#pragma unroll
            for (int j = 0; j < NC; j++) {
                ull bb = dupf(hs[cur][k][cg * NC + j]);
                ffma2(acc[j], a2, bb);
            }
        }
        __syncthreads();
    }
    Zred[t] = zacc;
    __syncthreads();
    if (t < TN) {
        float z = 0.f;
#pragma unroll
        for (int q = 0; q < G; q++) z += Zred[t + q * TN];
        Zs[t] = 1.f / z;
    }
    __syncthreads();
    {
        int lr0 = rg * MR;
        float zi0 = Zs[lr0], zi1 = Zs[lr0 + 1];
#pragma unroll
        for (int j = 0; j < NC; j++) {
            float2 v = unpack2(acc[j]);
            int d = cg * NC + j;
            g_h3[(size_t)(n0 + lr0) * 16 + d]     = eluf(v.x * zi0);
            g_h3[(size_t)(n0 + lr0 + 1) * 16 + d] = eluf(v.y * zi1);
        }
    }
}

// ---------------- final log-softmax ----------------
__global__ __launch_bounds__(256) void logsoftmax_k(float* __restrict__ out) {
    int n    = blockIdx.x * 8 + (threadIdx.x >> 5);
    int lane = threadIdx.x & 31;
    if (n >= NNODES) return;
    float v = (lane < 16) ? g_h3[n * 16 + lane] : -INFINITY;
    float m = v;
#pragma unroll
    for (int o = 16; o; o >>= 1) m = fmaxf(m, __shfl_xor_sync(~0u, m, o));
    float e = (lane < 16) ? expf(v - m) : 0.f;
    float s = e;
#pragma unroll
    for (int o = 16; o; o >>= 1) s += __shfl_xor_sync(~0u, s, o);
    if (lane < 16) out[n * 16 + lane] = v - m - logf(s);
}

// ---------------- launch ----------------
extern "C" void kernel_launch(void* const* d_in, const int* in_sizes, int n_in,
                              void* d_out, int out_size) {
    const float* x     = (const float*)d_in[0];
    const int*   adj   = (const int*)d_in[1];
    const float* W_in  = (const float*)d_in[2];
    const float* a_in  = (const float*)d_in[3];
    const float* W_hid = (const float*)d_in[4];
    const float* a_hid = (const float*)d_in[5];
    const float* W_out = (const float*)d_in[6];
    const float* a_out = (const float*)d_in[7];
    float* out = (float*)d_out;

    // smem: 2 B slots + 2 W bufs + 4 E slots (~62.5 KB -> 3 CTAs/SM)
    const int SMEM_L1 = 2 * (128 * 40 * 4) + 2 * (64 * 40 * 4)  + 4 * 256;  // 62464
    const int SMEM_L2 = 2 * (64 * 40 * 4)  + 2 * (128 * 40 * 4) + 4 * 256;  // 62464
    cudaFuncSetAttribute(aggW4_k<128, 64>, cudaFuncAttributeMaxDynamicSharedMemorySize, SMEM_L1);
    cudaFuncSetAttribute(aggW4_k<64, 128>, cudaFuncAttributeMaxDynamicSharedMemorySize, SMEM_L2);

    // Layer 1 (aggW4_k<128,64> is launch #4 -> ncu profiles it)
    gemm_k<64, 64, 4, 4, 0><<<dim3(64, 2, 4), 256>>>(x, W_in, 128, 128);          // 1
    scores_pack_k<<<2048 + 2048, 256>>>(a_in, 128, NHEADS * NNODES, adj, 2048);   // 2
    transpose_tf32_k<128><<<dim3(128, 4, 4), 256>>>();                            // 3
    aggW4_k<128, 64><<<dim3(64, 4, 2), 256, SMEM_L1>>>();                         // 4
    combine1_k<<<4096, 256>>>(x);                                                 // 5

    // Layer 2
    gemm_k<64, 64, 4, 4, 1><<<dim3(64, 1, 4), 256>>>(nullptr, W_hid, 512, 64);
    scores_k<<<(NHEADS * NNODES) / 8, 256>>>(a_hid, 64, NHEADS * NNODES);
    transpose_tf32_k<64><<<dim3(128, 2, 4), 256>>>();
    aggW4_k<64, 128><<<dim3(32, 4, 2), 256, SMEM_L2>>>();
    combine2_k<<<2048, 256>>>();

    // Layer 3
    gemm_k<64, 16, 4, 1, 2><<<dim3(64, 1, 1), 256>>>(nullptr, W_out, 256, 16);
    scores_k<<<NNODES / 8, 256>>>(a_out, 16, NNODES);
    agg3_k<<<dim3(128, 1, 1), 128>>>();

    logsoftmax_k<<<NNODES / 8, 256>>>(out);
}

// round 17
// speedup vs baseline: 1.9407x; 1.0936x over previous
#include <cuda_runtime.h>
#include <cuda_bf16.h>
#include <cstdint>
#include <math.h>

#define NNODES 4096
#define NW 128
#define NHEADS 4

typedef unsigned long long ull;

// ---------------- scratch ----------------
__device__ unsigned g_adjbits[NNODES * NW];
__device__ float g_hf[NHEADS * NNODES * 128];
__device__ float g_E1[NHEADS * NNODES];
__device__ float g_E1s[NHEADS * NNODES];
__device__ float g_E2a[NHEADS * NNODES];       // E2, pair-permuted within 32-blocks
__device__ float g_E2sa[NHEADS * NNODES];      // E2s, pair-permuted
__device__ float2 g_E2p[NHEADS * NNODES];      // (E2, E2s) natural order (agg3)
__device__ float g_cat1[NNODES * 512];
__device__ float g_cat2[NNODES * 256];
__device__ float g_h3[NNODES * 16];
__device__ float g_hT[NHEADS * 128 * NNODES];  // [h][d][m'], tf32, m pair-permuted
__device__ float g_part[4 * NHEADS * NNODES * 64];    // split partials (16MB, reused)
__device__ float g_pz[4 * NHEADS * NNODES];           // split Z partials

__device__ __forceinline__ float eluf(float v) { return v > 0.f ? v : expm1f(v); }

__device__ __forceinline__ uint32_t smem_u32(const void* p) {
    uint32_t a;
    asm("{ .reg .u64 t; cvta.to.shared.u64 t, %1; cvt.u32.u64 %0, t; }" : "=r"(a) : "l"(p));
    return a;
}
__device__ __forceinline__ uint32_t tf32u(float v) {
    uint32_t r;
    asm("cvt.rna.tf32.f32 %0, %1;" : "=r"(r) : "f"(v));
    return r;
}
__device__ __forceinline__ ull dupf(float v) {
    ull r; asm("mov.b64 %0, {%1, %1};" : "=l"(r) : "f"(v)); return r;
}
__device__ __forceinline__ void ffma2(ull& acc, ull a, ull b) {
    asm("fma.rn.f32x2 %0, %1, %2, %0;" : "+l"(acc) : "l"(a), "l"(b));
}
__device__ __forceinline__ ull mul2(ull a, ull b) {
    ull r; asm("mul.rn.f32x2 %0, %1, %2;" : "=l"(r) : "l"(a), "l"(b)); return r;
}
__device__ __forceinline__ float2 unpack2(ull v) {
    float2 r; asm("mov.b64 {%0, %1}, %2;" : "=f"(r.x), "=f"(r.y) : "l"(v)); return r;
}

#define CP16(dst, src) \
    asm volatile("cp.async.cg.shared.global [%0], [%1], 16;" :: "r"(dst), "l"(src))
#define CP_COMMIT() asm volatile("cp.async.commit_group;" ::: "memory")
#define CP_WAIT(n)  asm volatile("cp.async.wait_group %0;" :: "n"(n) : "memory")

__device__ __forceinline__ void mma_tf32(float* c, uint32_t a0, uint32_t a1,
                                         uint32_t a2, uint32_t a3,
                                         uint32_t b0, uint32_t b1) {
    asm volatile(
        "mma.sync.aligned.m16n8k8.row.col.f32.tf32.tf32.f32 "
        "{%0,%1,%2,%3}, {%4,%5,%6,%7}, {%8,%9}, {%0,%1,%2,%3};"
        : "+f"(c[0]), "+f"(c[1]), "+f"(c[2]), "+f"(c[3])
        : "r"(a0), "r"(a1), "r"(a2), "r"(a3), "r"(b0), "r"(b1));
}

// ---------------- feature GEMM (f32x2 inner product) ----------------
template<int TN, int TD, int MR, int NC, int SRC>
__global__ __launch_bounds__(256) void gemm_k(const float* __restrict__ Aext,
                                              const float* __restrict__ W,
                                              int K, int Dtot) {
    const int TK = 16;
    __shared__ __align__(16) float As[TK][TN];
    __shared__ __align__(16) float Bs[TK][TD];
    const float* A = (SRC == 0) ? Aext : (SRC == 1 ? g_cat1 : g_cat2);

    int t = threadIdx.x;
    int n0 = blockIdx.x * TN;
    int d0 = blockIdx.y * TD;
    int h  = blockIdx.z;
    const float* Wh = W + (size_t)h * K * Dtot;
    const int rg = t / (TD / NC);
    const int cg = t % (TD / NC);

    constexpr int NC2 = (NC & 1) ? 0 : NC / 2;
    ull accp[MR][NC2 ? NC2 : 1];
    float accs[MR][NC2 ? 1 : NC];
#pragma unroll
    for (int i = 0; i < MR; i++) {
        if (NC2) {
#pragma unroll
            for (int j = 0; j < (NC2 ? NC2 : 1); j++) accp[i][j] = 0ull;
        } else {
#pragma unroll
            for (int j = 0; j < (NC2 ? 1 : NC); j++) accs[i][j] = 0.f;
        }
    }

    for (int k0 = 0; k0 < K; k0 += TK) {
        for (int idx = t; idx < TN * (TK / 4); idx += 256) {
            int i_n = idx / (TK / 4);
            int k4  = idx % (TK / 4);
            float4 v = *(const float4*)&A[(size_t)(n0 + i_n) * K + k0 + 4 * k4];
            As[4 * k4 + 0][i_n] = v.x;
            As[4 * k4 + 1][i_n] = v.y;
            As[4 * k4 + 2][i_n] = v.z;
            As[4 * k4 + 3][i_n] = v.w;
        }
        for (int idx = t; idx < TK * (TD / 4); idx += 256) {
            int kk = idx / (TD / 4);
            int j4 = idx % (TD / 4);
            *(float4*)&Bs[kk][4 * j4] =
                *(const float4*)&Wh[(size_t)(k0 + kk) * Dtot + d0 + 4 * j4];
        }
        __syncthreads();
#pragma unroll
        for (int k = 0; k < TK; k++) {
            if (NC2) {
                ull bp[NC2 ? NC2 : 1];
#pragma unroll
                for (int j = 0; j < (NC2 ? NC2 : 1); j++)
                    bp[j] = *(const ull*)&Bs[k][cg * NC + 2 * j];
#pragma unroll
                for (int i = 0; i < MR; i++) {
                    ull ad = dupf(As[k][rg * MR + i]);
#pragma unroll
                    for (int j = 0; j < (NC2 ? NC2 : 1); j++)
                        ffma2(accp[i][j], ad, bp[j]);
                }
            } else {
                float a_[MR], b_[NC];
#pragma unroll
                for (int i = 0; i < MR; i++) a_[i] = As[k][rg * MR + i];
#pragma unroll
                for (int j = 0; j < NC; j++) b_[j] = Bs[k][cg * NC + j];
#pragma unroll
                for (int i = 0; i < MR; i++)
#pragma unroll
                    for (int j = 0; j < NC; j++)
                        accs[i][j] = fmaf(a_[i], b_[j], accs[i][j]);
            }
        }
        __syncthreads();
    }
    float* Ch = g_hf + (size_t)h * NNODES * Dtot;
#pragma unroll
    for (int i = 0; i < MR; i++) {
        float* row = &Ch[(size_t)(n0 + rg * MR + i) * Dtot + d0 + cg * NC];
        if (NC2) {
#pragma unroll
            for (int j = 0; j < (NC2 ? NC2 : 1); j++) {
                float2 v = unpack2(accp[i][j]);
                row[2 * j]     = v.x;
                row[2 * j + 1] = v.y;
            }
        } else {
#pragma unroll
            for (int j = 0; j < (NC2 ? 1 : NC); j++) row[j] = accs[i][j];
        }
    }
}

// ---------------- scores ----------------
__device__ __forceinline__ void scores_body(const float* a, int D, int total,
                                            int blk, int t) {
    int gid  = blk * 8 + (t >> 5);
    int lane = t & 31;
    if (gid >= total) return;
    int h = gid / NNODES, n = gid % NNODES;
    const float* hr = g_hf + ((size_t)h * NNODES + n) * D;
    const float* a1 = a + (size_t)h * 2 * D;
    const float* a2 = a1 + D;
    float s1 = 0.f, s2 = 0.f;
    for (int d = lane; d < D; d += 32) {
        float v = hr[d];
        s1 += v * a1[d];
        s2 += v * a2[d];
    }
#pragma unroll
    for (int o = 16; o; o >>= 1) {
        s1 += __shfl_xor_sync(~0u, s1, o);
        s2 += __shfl_xor_sync(~0u, s2, o);
    }
    if (!lane) {
        int idx = h * NNODES + n;
        float e2  = expf(s2);
        float e2s = expf(0.2f * s2);
        g_E1[idx]  = expf(s1);
        g_E1s[idx] = expf(0.2f * s1);
        g_E2p[idx] = make_float2(e2, e2s);
        int j  = n & 31;
        int jp = (j & 24) | (2 * (j & 3) + ((j >> 2) & 1));
        int idxp = (idx & ~31) | jp;
        g_E2a[idxp]  = e2;
        g_E2sa[idxp] = e2s;
    }
}

__global__ __launch_bounds__(256) void scores_k(const float* __restrict__ a, int D, int total) {
    scores_body(a, D, total, blockIdx.x, threadIdx.x);
}

__global__ __launch_bounds__(256) void scores_pack_k(const float* __restrict__ a, int D,
                                                     int total, const int* __restrict__ adj,
                                                     int scoreBlocks) {
    if ((int)blockIdx.x < scoreBlocks) {
        scores_body(a, D, total, blockIdx.x, threadIdx.x);
        return;
    }
    int wi = (blockIdx.x - scoreBlocks) * 256 + threadIdx.x;
    if (wi >= NNODES * NW) return;
    const int4* p = (const int4*)adj + (size_t)wi * 8;
    unsigned w = 0;
#pragma unroll
    for (int q = 0; q < 8; q++) {
        int4 v = p[q];
        if (v.x > 0) w |= 1u << (q * 4 + 0);
        if (v.y > 0) w |= 1u << (q * 4 + 1);
        if (v.z > 0) w |= 1u << (q * 4 + 2);
        if (v.w > 0) w |= 1u << (q * 4 + 3);
    }
    g_adjbits[wi] = w;
}

// ---------------- transpose + tf32 + m-pair-permute ----------------
template<int D>
__global__ __launch_bounds__(256) void transpose_tf32_k() {
    __shared__ float ts[32][33];
    int t  = threadIdx.x;
    int nt = blockIdx.x, dt = blockIdx.y, h = blockIdx.z;
    int r0 = t / 32, c = t % 32;
#pragma unroll
    for (int p = 0; p < 4; p++) {
        int r = p * 8 + r0;
        ts[r][c] = g_hf[((size_t)h * NNODES + nt * 32 + r) * D + dt * 32 + c];
    }
    __syncthreads();
    const int cperm = (c & ~7) + 2 * (c & 3) + ((c >> 2) & 1);
#pragma unroll
    for (int p = 0; p < 4; p++) {
        int dr = p * 8 + r0;
        uint32_t v = tf32u(ts[c][dr]);
        size_t addr = ((size_t)h * D + dt * 32 + dr) * NNODES + nt * 32 + cperm;
        g_hT[addr] = __uint_as_float(v);
    }
}

// ---------------- tf32 mma aggregation: m-split, 2 B-slots, slim weights ----
// grid (ntiles, head, z) ; z = m-split index. Partials (raw acc + Z) to gmem.
template<int D, int ROWS, int MSPLIT>
__global__ __launch_bounds__(256) void aggW4_k() {
    constexpr int NCG  = D / 32;
    constexpr int NCH  = (NNODES / 32) / MSPLIT;
    constexpr int BST  = 40;
    constexpr int BBUF = D * BST * 4;
    constexpr int WBUF = ROWS * BST * 4;
    constexpr int O_W  = 2 * BBUF;
    constexpr int O_E  = O_W + 2 * WBUF;
    constexpr int ESL  = 256;
    constexpr int R    = ROWS / 64;

    extern __shared__ __align__(16) char sm[];
    const uint32_t sb = smem_u32(sm);

    const int t = threadIdx.x, lane = t & 31, wid = t >> 5;
    const int cg = wid % NCG, rg = wid / NCG;
    const int n0 = blockIdx.x * ROWS;
    const int head = blockIdx.y;
    const int zz = blockIdx.z;
    const int cbase = zz * NCH;
    const int headN = head * NNODES;
    const int rq  = lane >> 2;
    const int k0b = lane & 3;
    const int i4  = t & 3;
    const int wr0 = t >> 2;

    ull e1d[R], e1sd[R];
    const unsigned* adjp[R];
#pragma unroll
    for (int r = 0; r < R; r++) {
        int row = wr0 + r * 64;
        e1d[r]  = dupf(g_E1[headN + n0 + row]);
        e1sd[r] = dupf(g_E1s[headN + n0 + row]);
        adjp[r] = g_adjbits + (size_t)(n0 + row) * NW + cbase;
    }
    float zacc[R];
#pragma unroll
    for (int r = 0; r < R; r++) zacc[r] = 0.f;

    float acc[2][4][4];
#pragma unroll
    for (int mg = 0; mg < 2; mg++)
#pragma unroll
        for (int ng = 0; ng < 4; ng++)
#pragma unroll
            for (int q = 0; q < 4; q++) acc[mg][ng][q] = 0.f;

    auto fillB = [&](int ch) {
        for (int idx = t; idx < D * 8; idx += 256) {
            int row = idx >> 3, c8 = idx & 7;
            uint32_t dst = sb + (uint32_t)((ch & 1) * BBUF + (row * BST + c8 * 4) * 4);
            size_t s = ((size_t)(head * D + row)) * NNODES + (cbase + ch) * 32 + c8 * 4;
            CP16(dst, (const void*)(g_hT + s));
        }
    };
    auto fillE = [&](int ch) {
        if (t < 8) {
            uint32_t dst = sb + (uint32_t)(O_E + (ch & 3) * ESL + t * 16);
            CP16(dst, (const void*)(g_E2a + headN + (cbase + ch) * 32 + t * 4));
        } else if (t < 16) {
            uint32_t dst = sb + (uint32_t)(O_E + (ch & 3) * ESL + 128 + (t - 8) * 16);
            CP16(dst, (const void*)(g_E2sa + headN + (cbase + ch) * 32 + (t - 8) * 4));
        }
    };
    auto weights = [&](int ch, const unsigned* mwv) {
        const float* e2a  = (const float*)(sm + O_E + (ch & 3) * ESL);
        const float* e2sa = e2a + 32;
        float* Wb = (float*)(sm + O_W + (ch & 1) * WBUF);
#pragma unroll
        for (int r = 0; r < R; r++) {
            unsigned msh = mwv[r] >> i4;
            float* wrow = Wb + (wr0 + r * 64) * BST;
            float zl = 0.f;
#pragma unroll
            for (int blk = 0; blk < 4; blk++) {
                ull q1 = *(const ull*)&e2a[blk * 8 + 2 * i4];
                ull q2 = *(const ull*)&e2sa[blk * 8 + 2 * i4];
                float2 A  = unpack2(mul2(e1d[r], q1));
                float2 Bv = unpack2(mul2(e1sd[r], q2));
                float w0 = fmaxf(A.x, Bv.x);
                float w1 = fmaxf(A.y, Bv.y);
                w0 = (msh & (1u << (blk * 8)))     ? w0 : 0.f;
                w1 = (msh & (1u << (blk * 8 + 4))) ? w1 : 0.f;
                zl += w0 + w1;
                *(float2*)&wrow[blk * 8 + 2 * i4] =
                    make_float2(__uint_as_float(tf32u(w0)), __uint_as_float(tf32u(w1)));
            }
            zacc[r] += zl;
        }
    };
    auto mmastep = [&](int ch) {
        const float* Bs = (const float*)(sm + (ch & 1) * BBUF);
        const float* Wb = (const float*)(sm + O_W + (ch & 1) * WBUF);
#pragma unroll
        for (int ks = 0; ks < 4; ks++) {
            const int cw = ks * 8 + 2 * k0b;
            uint2 a0[2], a1[2];
#pragma unroll
            for (int mg = 0; mg < 2; mg++) {
                const float* w0 = Wb + (rg * 32 + mg * 16 + rq) * BST + cw;
                a0[mg] = *(const uint2*)w0;
                a1[mg] = *(const uint2*)(w0 + 8 * BST);
            }
#pragma unroll
            for (int ng = 0; ng < 4; ng++) {
                const float* bp = Bs + (cg * 32 + ng * 8 + rq) * BST + cw;
                uint2 b = *(const uint2*)bp;
#pragma unroll
                for (int mg = 0; mg < 2; mg++)
                    mma_tf32(acc[mg][ng], a0[mg].x, a1[mg].x, a0[mg].y, a1[mg].y,
                             b.x, b.y);
            }
        }
    };

    unsigned mw0[R], mwc[R], mwn[R];
#pragma unroll
    for (int r = 0; r < R; r++) {
        mw0[r] = adjp[r][0];
        mwc[r] = adjp[r][1];
        mwn[r] = adjp[r][2];
    }

    fillB(0); fillE(0); fillE(1); CP_COMMIT();
    CP_WAIT(0); __syncthreads();
    weights(0, mw0);

    for (int c = 0; c < NCH; c++) {
        __syncthreads();
        if (c + 1 < NCH) {
            fillB(c + 1);
            if (c + 2 < NCH) fillE(c + 2);
            CP_COMMIT(); CP_WAIT(1);
            weights(c + 1, mwc);
#pragma unroll
            for (int r = 0; r < R; r++) mwc[r] = mwn[r];
            if (c + 3 < NCH) {
#pragma unroll
                for (int r = 0; r < R; r++) mwn[r] = adjp[r][c + 3];
            }
        } else {
            CP_WAIT(0);
        }
        mmastep(c);
    }

#pragma unroll
    for (int r = 0; r < R; r++) {
        float z = zacc[r];
        z += __shfl_xor_sync(~0u, z, 1);
        z += __shfl_xor_sync(~0u, z, 2);
        if (i4 == 0)
            g_pz[(size_t)(zz * NHEADS + head) * NNODES + n0 + wr0 + r * 64] = z;
    }

    float* P = g_part + ((size_t)(zz * NHEADS + head) * NNODES) * D;
#pragma unroll
    for (int mg = 0; mg < 2; mg++) {
        int lr = rg * 32 + mg * 16 + rq;
        int n = n0 + lr;
#pragma unroll
        for (int ng = 0; ng < 4; ng++) {
            int col = cg * 32 + ng * 8 + (lane & 3) * 2;
            *(float2*)&P[(size_t)n * D + col]       = make_float2(acc[mg][ng][0], acc[mg][ng][1]);
            *(float2*)&P[(size_t)(n + 8) * D + col] = make_float2(acc[mg][ng][2], acc[mg][ng][3]);
        }
    }
}

// ---------------- combine kernels ----------------
__global__ __launch_bounds__(256) void combine1_k(const float* __restrict__ x) {
    int e = blockIdx.x * 256 + threadIdx.x;       // float2 over 4*4096*64
    int h = e >> 18;
    int r = e & 0x3FFFF;
    int n = r >> 6;
    int d2 = r & 63;
    const float2* P = (const float2*)g_part;
    size_t i0 = ((size_t)h * NNODES + n) * 64 + d2;
    size_t i1 = i0 + (size_t)NHEADS * NNODES * 64;
    float2 a = P[i0], b = P[i1];
    float zi = 1.f / (g_pz[(size_t)h * NNODES + n] +
                      g_pz[(size_t)(NHEADS + h) * NNODES + n]);
    float2 rx = *(const float2*)&x[(size_t)n * 128 + 2 * d2];
    float2 o;
    o.x = eluf((a.x + b.x) * zi + rx.x);
    o.y = eluf((a.y + b.y) * zi + rx.y);
    *(float2*)&g_cat1[(size_t)n * 512 + h * 128 + 2 * d2] = o;
}

__global__ __launch_bounds__(256) void combine2_k() {
    int e = blockIdx.x * 256 + threadIdx.x;       // float2 over 4*4096*32
    int h = e >> 17;
    int r = e & 0x1FFFF;
    int n = r >> 5;
    int d2 = r & 31;
    const float2* P = (const float2*)g_part;
    float2 s = make_float2(0.f, 0.f);
    float z = 0.f;
#pragma unroll
    for (int q = 0; q < 4; q++) {
        float2 v = P[((size_t)(q * NHEADS + h) * NNODES + n) * 32 + d2];
        s.x += v.x; s.y += v.y;
        z += g_pz[(size_t)(q * NHEADS + h) * NNODES + n];
    }
    float zi = 1.f / z;
    float2 o;
    o.x = eluf(s.x * zi);
    o.y = eluf(s.y * zi);
    *(float2*)&g_cat2[(size_t)n * 256 + h * 64 + 2 * d2] = o;
}

// ---------------- SIMT agg for layer 3 (D=16), m-split partials ----------------
__global__ __launch_bounds__(128) void agg3p_k() {
    const int D = 16, TN = 32, TM = 32, MR = 2, NC = 2;
    __shared__ __align__(16) float hs[2][TM][D];
    __shared__ __align__(16) float ws[2][TM][TN + 2];
    __shared__ float Zred[128];

    const int t  = threadIdx.x;
    const int n0 = blockIdx.x * TN;
    const int zz = blockIdx.y;                  // m-split 0..3
    const int mbase = zz * (NNODES / 4);
    const float* hfh = g_hf;

    const int rA = t % TN;
    const int G  = 128 / TN;
    const int g  = t / TN;
    const int MMPT = TM / G;

    const float rE1  = g_E1[n0 + rA];
    const float rE1s = g_E1s[n0 + rA];
    float zacc = 0.f;

    const int rg = t / (D / NC);
    const int cg = t % (D / NC);

    ull acc[NC];
#pragma unroll
    for (int j = 0; j < NC; j++) acc[j] = 0ull;

    auto fill = [&](int wti, int buf) {
        int m0 = mbase + wti * TM;
        for (int idx = t; idx < TM * (D / 4); idx += 128) {
            int m  = idx / (D / 4);
            int dd = idx % (D / 4);
            *(float4*)&hs[buf][m][4 * dd] = *(const float4*)&hfh[(size_t)(m0 + m) * D + 4 * dd];
        }
        unsigned aw = g_adjbits[(size_t)(n0 + rA) * NW + (mbase / 32) + wti];
#pragma unroll
        for (int j = 0; j < MMPT; j++) {
            int mm = g + G * j;
            float w = 0.f;
            if ((aw >> mm) & 1u) {
                float2 ep = g_E2p[m0 + mm];
                w = fmaxf(rE1 * ep.x, rE1s * ep.y);
            }
            ws[buf][mm][rA] = w;
            zacc += w;
        }
    };

    fill(0, 0);
    __syncthreads();
    const int NT = (NNODES / 4) / TM;
    for (int mt = 0; mt < NT; mt++) {
        int cur = mt & 1;
        if (mt + 1 < NT) fill(mt + 1, cur ^ 1);
#pragma unroll
        for (int k = 0; k < TM; k++) {
            ull a2 = *(const ull*)&ws[cur][k][rg * MR];
#pragma unroll
            for (int j = 0; j < NC; j++) {
                ull bb = dupf(hs[cur][k][cg * NC + j]);
                ffma2(acc[j], a2, bb);
            }
        }
        __syncthreads();
    }
    Zred[t] = zacc;
    __syncthreads();
    if (t < TN) {
        float z = 0.f;
#pragma unroll
        for (int q = 0; q < G; q++) z += Zred[t + q * TN];
        g_pz[(size_t)zz * NNODES + n0 + t] = z;
    }
    // raw partial numerator
    float* P = g_part + (size_t)zz * NNODES * 16;
    {
        int lr0 = rg * MR;
#pragma unroll
        for (int j = 0; j < NC; j++) {
            float2 v = unpack2(acc[j]);
            int d = cg * NC + j;
            P[(size_t)(n0 + lr0) * 16 + d]     = v.x;
            P[(size_t)(n0 + lr0 + 1) * 16 + d] = v.y;
        }
    }
}

__global__ __launch_bounds__(256) void combine3_k() {
    int e = blockIdx.x * 256 + threadIdx.x;       // over 4096*16
    int n = e >> 4, d = e & 15;
    float s = 0.f, z = 0.f;
#pragma unroll
    for (int q = 0; q < 4; q++) {
        s += g_part[(size_t)q * NNODES * 16 + (size_t)n * 16 + d];
        z += g_pz[(size_t)q * NNODES + n];
    }
    g_h3[(size_t)n * 16 + d] = eluf(s / z);
}

// ---------------- final log-softmax ----------------
__global__ __launch_bounds__(256) void logsoftmax_k(float* __restrict__ out) {
    int n    = blockIdx.x * 8 + (threadIdx.x >> 5);
    int lane = threadIdx.x & 31;
    if (n >= NNODES) return;
    float v = (lane < 16) ? g_h3[n * 16 + lane] : -INFINITY;
    float m = v;
#pragma unroll
    for (int o = 16; o; o >>= 1) m = fmaxf(m, __shfl_xor_sync(~0u, m, o));
    float e = (lane < 16) ? expf(v - m) : 0.f;
    float s = e;
#pragma unroll
    for (int o = 16; o; o >>= 1) s += __shfl_xor_sync(~0u, s, o);
    if (lane < 16) out[n * 16 + lane] = v - m - logf(s);
}

// ---------------- launch ----------------
extern "C" void kernel_launch(void* const* d_in, const int* in_sizes, int n_in,
                              void* d_out, int out_size) {
    const float* x     = (const float*)d_in[0];
    const int*   adj   = (const int*)d_in[1];
    const float* W_in  = (const float*)d_in[2];
    const float* a_in  = (const float*)d_in[3];
    const float* W_hid = (const float*)d_in[4];
    const float* a_hid = (const float*)d_in[5];
    const float* W_out = (const float*)d_in[6];
    const float* a_out = (const float*)d_in[7];
    float* out = (float*)d_out;

    const int SMEM_L1 = 2 * (128 * 40 * 4) + 2 * (64 * 40 * 4)  + 4 * 256;  // 62464
    const int SMEM_L2 = 2 * (64 * 40 * 4)  + 2 * (128 * 40 * 4) + 4 * 256;  // 62464
    cudaFuncSetAttribute(aggW4_k<128, 64, 2>, cudaFuncAttributeMaxDynamicSharedMemorySize, SMEM_L1);
    cudaFuncSetAttribute(aggW4_k<64, 128, 4>, cudaFuncAttributeMaxDynamicSharedMemorySize, SMEM_L2);

    // Layer 1 (aggW4_k<128,64,2> is launch #4 -> ncu profiles it)
    gemm_k<64, 64, 4, 4, 0><<<dim3(64, 2, 4), 256>>>(x, W_in, 128, 128);          // 1
    scores_pack_k<<<2048 + 2048, 256>>>(a_in, 128, NHEADS * NNODES, adj, 2048);   // 2
    transpose_tf32_k<128><<<dim3(128, 4, 4), 256>>>();                            // 3
    aggW4_k<128, 64, 2><<<dim3(64, 4, 2), 256, SMEM_L1>>>();                      // 4
    combine1_k<<<4096, 256>>>(x);                                                 // 5

    // Layer 2
    gemm_k<64, 64, 4, 4, 1><<<dim3(64, 1, 4), 256>>>(nullptr, W_hid, 512, 64);
    scores_k<<<(NHEADS * NNODES) / 8, 256>>>(a_hid, 64, NHEADS * NNODES);
    transpose_tf32_k<64><<<dim3(128, 2, 4), 256>>>();
    aggW4_k<64, 128, 4><<<dim3(32, 4, 4), 256, SMEM_L2>>>();
    combine2_k<<<2048, 256>>>();

    // Layer 3
    gemm_k<64, 16, 4, 1, 2><<<dim3(64, 1, 1), 256>>>(nullptr, W_out, 256, 16);
    scores_k<<<NNODES / 8, 256>>>(a_out, 16, NNODES);
    agg3p_k<<<dim3(128, 4), 128>>>();
    combine3_k<<<256, 256>>>();

    logsoftmax_k<<<NNODES / 8, 256>>>(out);
}